// round 11
// baseline (speedup 1.0000x reference)
#include <cuda_runtime.h>
#include <cuda_fp16.h>
#include <math.h>

#define NN 100000
#define EE 1600000
#define DD 64
#define CSRCAP 2000000   // EE + 3*NN + slack (CSR padded to multiples of 4)

// ---------------- scratch (device globals; no allocation allowed) ----------
// Zero-initialized at module load; pad_k re-zeroes g_counts/g_flag each launch
// AFTER their last use, so every graph replay sees zeros.
__device__ __half2 g_h16[(size_t)(NN + 1) * 32]; // fp16 mirror of X@W; row NN stays 0 (sentinel)
__device__ float   g_z[(size_t)NN * DD];         // layer-1 output (fp32)
__device__ float   g_as[NN + 1];                 // [NN] = -1e38 sentinel
__device__ float   g_ad[NN];
__device__ int     g_counts[NN];
__device__ int     g_offs[NN + 1];
__device__ __align__(16) int g_rank[EE];         // edge rank within its dst bucket
__device__ __align__(16) int g_csr[CSRCAP];
__device__ int     g_flag[128];
__device__ int     g_aggv[128];
__device__ int     g_prefv[128];

// ---------------- packed f32x2 helpers -------------------------------------
__device__ __forceinline__ unsigned long long dup2(float v) {
    unsigned long long r;
    asm("mov.b64 %0, {%1, %1};" : "=l"(r) : "f"(v));
    return r;
}
__device__ __forceinline__ unsigned long long fma2(unsigned long long a,
                                                   unsigned long long b,
                                                   unsigned long long c) {
    unsigned long long d;
    asm("fma.rn.f32x2 %0, %1, %2, %3;" : "=l"(d) : "l"(a), "l"(b), "l"(c));
    return d;
}
__device__ __forceinline__ void unpack2(unsigned long long v, float& lo, float& hi) {
    asm("mov.b64 {%0, %1}, %2;" : "=f"(lo), "=f"(hi) : "l"(v));
}

// ---------------- hist: count + record per-edge rank -----------------------
__global__ void hist_k(const int4* __restrict__ dst4) {
    int i = blockIdx.x * blockDim.x + threadIdx.x;
    if (i < EE / 4) {
        int4 d = dst4[i];
        int4 r;
        r.x = atomicAdd(&g_counts[d.x], 1);
        r.y = atomicAdd(&g_counts[d.y], 1);
        r.z = atomicAdd(&g_counts[d.z], 1);
        r.w = atomicAdd(&g_counts[d.w], 1);
        *(int4*)&g_rank[i * 4] = r;
    }
}

// ---------------- fused scan, warp-parallel decoupled lookback -------------
__global__ void __launch_bounds__(256) scan_k() {
    __shared__ int warpSums[8];
    __shared__ int sPrefix;
    int b = blockIdx.x, t = threadIdx.x;
    int base = b * 1024 + t * 4;
    int c0 = (base + 0 < NN) ? ((g_counts[base + 0] + 3) & ~3) : 0;
    int c1 = (base + 1 < NN) ? ((g_counts[base + 1] + 3) & ~3) : 0;
    int c2 = (base + 2 < NN) ? ((g_counts[base + 2] + 3) & ~3) : 0;
    int c3 = (base + 3 < NN) ? ((g_counts[base + 3] + 3) & ~3) : 0;
    int tsum = c0 + c1 + c2 + c3;
    int lane = t & 31, wid = t >> 5;
    int v = tsum;
    #pragma unroll
    for (int d = 1; d < 32; d <<= 1) {
        int n = __shfl_up_sync(0xffffffffu, v, d);
        if (lane >= d) v += n;
    }
    if (lane == 31) warpSums[wid] = v;
    __syncthreads();
    if (wid == 0 && lane < 8) {
        int wv = warpSums[lane];
        #pragma unroll
        for (int d = 1; d < 8; d <<= 1) {
            int n = __shfl_up_sync(0xffu, wv, d);
            if (lane >= d) wv += n;
        }
        warpSums[lane] = wv;
    }
    __syncthreads();
    if (wid == 0) {
        int T = warpSums[7];
        if (b == 0) {
            if (lane == 0) {
                g_prefv[0] = T;
                __threadfence();
                *(volatile int*)&g_flag[0] = 2;
                sPrefix = 0;
            }
        } else {
            if (lane == 0) {
                g_aggv[b] = T;
                __threadfence();
                *(volatile int*)&g_flag[b] = 1;
            }
            int run = 0;
            int baseJ = b - 1;
            while (true) {
                int j = baseJ - lane;
                int f = (j >= 0) ? *(volatile int*)&g_flag[j] : 3;
                while (__any_sync(0xffffffffu, f == 0)) {
                    if (f == 0) f = *(volatile int*)&g_flag[j];
                }
                __threadfence();
                int val = 0;
                if (j >= 0) val = (f == 2) ? g_prefv[j] : g_aggv[j];
                unsigned m2 = __ballot_sync(0xffffffffu, (j >= 0) && (f == 2));
                int stopLane = m2 ? (__ffs(m2) - 1) : 32;
                int contrib = (lane <= stopLane && j >= 0) ? val : 0;
                #pragma unroll
                for (int o = 16; o > 0; o >>= 1)
                    contrib += __shfl_down_sync(0xffffffffu, contrib, o);
                contrib = __shfl_sync(0xffffffffu, contrib, 0);
                run += contrib;
                if (m2) break;
                baseJ -= 32;
            }
            if (lane == 0) {
                sPrefix = run;
                g_prefv[b] = run + T;
                __threadfence();
                *(volatile int*)&g_flag[b] = 2;
            }
        }
    }
    __syncthreads();
    int exc = v - tsum + (wid > 0 ? warpSums[wid - 1] : 0) + sPrefix;
    int e0 = exc, e1 = exc + c0, e2 = e1 + c1, e3 = e2 + c2;
    if (base + 0 < NN) g_offs[base + 0] = e0;
    if (base + 1 < NN) g_offs[base + 1] = e1;
    if (base + 2 < NN) g_offs[base + 2] = e2;
    if (base + 3 < NN) g_offs[base + 3] = e3;
    if (base + 0 == NN - 1) g_offs[NN] = e1;
    if (base + 1 == NN - 1) g_offs[NN] = e2;
    if (base + 2 == NN - 1) g_offs[NN] = e3;
    if (base + 3 == NN - 1) g_offs[NN] = e3 + c3;
}

// sentinels into <=3 padding slots per node; re-zero counts+flags for replay.
// Touches ONLY padding slots -> safe to run concurrently with scatter_k.
__global__ void pad_k() {
    int i = blockIdx.x * blockDim.x + threadIdx.x;
    if (i == 0) g_as[NN] = -1e38f;
    if (i < 128) g_flag[i] = 0;
    if (i < NN) {
        int c = g_counts[i];
        int start = g_offs[i] + c;
        int end = g_offs[i + 1];
        for (int k = start; k < end; k++) g_csr[k] = NN;
        g_counts[i] = 0;
    }
}

// ---------------- scatter: NO atomics (rank precomputed) -------------------
__global__ void scatter_k(const int4* __restrict__ src4, const int4* __restrict__ dst4) {
    int i = blockIdx.x * blockDim.x + threadIdx.x;
    if (i < EE / 4) {
        int4 s = *(const int4*)&src4[i];
        int4 d = *(const int4*)&dst4[i];
        int4 r = *(const int4*)&g_rank[i * 4];
        g_csr[__ldg(&g_offs[d.x]) + r.x] = s.x;
        g_csr[__ldg(&g_offs[d.y]) + r.y] = s.y;
        g_csr[__ldg(&g_offs[d.z]) + r.z] = s.z;
        g_csr[__ldg(&g_offs[d.w]) + r.w] = s.w;
    }
}

// ---------------- dense: H16 = fp16(X@W), a_s, a_d -------------------------
// 256 threads, 128 rows x 64 cols per block, 8x4 outputs/thread, fma2.
__global__ void __launch_bounds__(256) gemm_att_k(
    const float* __restrict__ X, const float* __restrict__ W,
    const float* __restrict__ attS, const float* __restrict__ attD,
    __half2* __restrict__ H16, float* __restrict__ AS, float* __restrict__ AD)
{
    __shared__ float sW[64 * 64];        // [k][c]
    __shared__ float sXT[64 * 130];      // [k][r], 128 rows + pad
    __shared__ float sAtt[128];
    int tid = threadIdx.x;
    int rowBase = blockIdx.x * 128;

    #pragma unroll
    for (int i = 0; i < 4; i++)
        ((float4*)sW)[tid + 256 * i] = ((const float4*)W)[tid + 256 * i];
    if (tid < 128) sAtt[tid] = (tid < 64) ? attS[tid] : attD[tid - 64];

    {
        int r = tid >> 1;                 // 0..127
        int k0 = (tid & 1) * 32;          // 0 or 32
        int grow = rowBase + r;
        bool rv = grow < NN;
        const float4* xp = (const float4*)(X + (size_t)(rv ? grow : 0) * 64) + (k0 >> 2);
        #pragma unroll
        for (int i = 0; i < 8; i++) {
            float4 v = rv ? xp[i] : make_float4(0.f, 0.f, 0.f, 0.f);
            int kb = k0 + 4 * i;
            sXT[(kb + 0) * 130 + r] = v.x;
            sXT[(kb + 1) * 130 + r] = v.y;
            sXT[(kb + 2) * 130 + r] = v.z;
            sXT[(kb + 3) * 130 + r] = v.w;
        }
    }
    __syncthreads();

    int cg = (tid & 15) * 4;      // 16 col groups x 4 cols
    int rg = (tid >> 4) * 8;      // 16 row groups x 8 rows

    unsigned long long acc[4][4];
    #pragma unroll
    for (int a = 0; a < 4; a++)
        #pragma unroll
        for (int b = 0; b < 4; b++) acc[a][b] = 0ull;

    #pragma unroll 2
    for (int k = 0; k < 64; k++) {
        const float* xb = &sXT[k * 130 + rg];
        unsigned long long x01 = *(const unsigned long long*)(xb);
        unsigned long long x23 = *(const unsigned long long*)(xb + 2);
        unsigned long long x45 = *(const unsigned long long*)(xb + 4);
        unsigned long long x67 = *(const unsigned long long*)(xb + 6);
        float4 wv = *(const float4*)(&sW[(k << 6) + cg]);
        unsigned long long w0 = dup2(wv.x), w1 = dup2(wv.y);
        unsigned long long w2 = dup2(wv.z), w3 = dup2(wv.w);
        acc[0][0] = fma2(x01, w0, acc[0][0]);
        acc[0][1] = fma2(x01, w1, acc[0][1]);
        acc[0][2] = fma2(x01, w2, acc[0][2]);
        acc[0][3] = fma2(x01, w3, acc[0][3]);
        acc[1][0] = fma2(x23, w0, acc[1][0]);
        acc[1][1] = fma2(x23, w1, acc[1][1]);
        acc[1][2] = fma2(x23, w2, acc[1][2]);
        acc[1][3] = fma2(x23, w3, acc[1][3]);
        acc[2][0] = fma2(x45, w0, acc[2][0]);
        acc[2][1] = fma2(x45, w1, acc[2][1]);
        acc[2][2] = fma2(x45, w2, acc[2][2]);
        acc[2][3] = fma2(x45, w3, acc[2][3]);
        acc[3][0] = fma2(x67, w0, acc[3][0]);
        acc[3][1] = fma2(x67, w1, acc[3][1]);
        acc[3][2] = fma2(x67, w2, acc[3][2]);
        acc[3][3] = fma2(x67, w3, acc[3][3]);
    }

    float hv[8][4];
    #pragma unroll
    for (int rp = 0; rp < 4; rp++)
        #pragma unroll
        for (int c = 0; c < 4; c++)
            unpack2(acc[rp][c], hv[2 * rp][c], hv[2 * rp + 1][c]);

    float pas[8], pad_[8];
    #pragma unroll
    for (int r = 0; r < 8; r++) {
        float s = 0.f, d = 0.f;
        #pragma unroll
        for (int c = 0; c < 4; c++) {
            s = fmaf(hv[r][c], sAtt[cg + c], s);
            d = fmaf(hv[r][c], sAtt[64 + cg + c], d);
        }
        pas[r] = s; pad_[r] = d;
    }
    #pragma unroll
    for (int off = 8; off >= 1; off >>= 1) {
        #pragma unroll
        for (int r = 0; r < 8; r++) {
            pas[r]  += __shfl_xor_sync(0xffffffffu, pas[r],  off, 16);
            pad_[r] += __shfl_xor_sync(0xffffffffu, pad_[r], off, 16);
        }
    }
    if ((tid & 15) == 0) {
        #pragma unroll
        for (int r = 0; r < 8; r++) {
            int grow = rowBase + rg + r;
            if (grow < NN) { AS[grow] = pas[r]; AD[grow] = pad_[r]; }
        }
    }
    #pragma unroll
    for (int r = 0; r < 8; r++) {
        int grow = rowBase + rg + r;
        if (grow < NN) {
            union { __half2 h[2]; uint2 u; } cv;
            cv.h[0] = __floats2half2_rn(hv[r][0], hv[r][1]);
            cv.h[1] = __floats2half2_rn(hv[r][2], hv[r][3]);
            *(uint2*)(H16 + (size_t)grow * 32 + (cg >> 1)) = cv.u;
        }
    }
}

// ---------------- sparse aggregate: warp per dst, simple 4-edge loop -------
// __launch_bounds__(256, 8): cap regs at 32 -> 64 resident warps/SM for
// cross-warp latency hiding (the binding constraint per issue-budget model).
__global__ void __launch_bounds__(256, 8) aggregate_k(
    const __half2* __restrict__ H16,
    const float* __restrict__ bias,
    float* __restrict__ OUT, int do_relu)
{
    int dst = (blockIdx.x * blockDim.x + threadIdx.x) >> 5;
    int lane = threadIdx.x & 31;
    if (dst >= NN) return;
    int j0 = __ldg(&g_offs[dst]);
    int j1 = __ldg(&g_offs[dst + 1]);
    float ad = __ldg(&g_ad[dst]);
    float s = 0.f, a0 = 0.f, a1 = 0.f;

    for (int j = j0; j < j1; j += 4) {
        int4 i4 = *(const int4*)&g_csr[j];          // uniform LDG.128
        float e0 = __ldg(&g_as[i4.x]) + ad;
        float e1 = __ldg(&g_as[i4.y]) + ad;
        float e2 = __ldg(&g_as[i4.z]) + ad;
        float e3 = __ldg(&g_as[i4.w]) + ad;
        __half2 v0 = __ldg(H16 + ((size_t)i4.x << 5) + lane);
        __half2 v1 = __ldg(H16 + ((size_t)i4.y << 5) + lane);
        __half2 v2 = __ldg(H16 + ((size_t)i4.z << 5) + lane);
        __half2 v3 = __ldg(H16 + ((size_t)i4.w << 5) + lane);
        e0 = e0 > 0.f ? e0 : 0.2f * e0;
        e1 = e1 > 0.f ? e1 : 0.2f * e1;
        e2 = e2 > 0.f ? e2 : 0.2f * e2;
        e3 = e3 > 0.f ? e3 : 0.2f * e3;
        float w0 = __expf(fminf(e0, 70.f));   // sentinel edges -> w=0
        float w1 = __expf(fminf(e1, 70.f));
        float w2 = __expf(fminf(e2, 70.f));
        float w3 = __expf(fminf(e3, 70.f));
        s += (w0 + w1) + (w2 + w3);
        float2 f0 = __half22float2(v0);
        float2 f1 = __half22float2(v1);
        float2 f2 = __half22float2(v2);
        float2 f3 = __half22float2(v3);
        a0 = fmaf(w0, f0.x, a0); a1 = fmaf(w0, f0.y, a1);
        a0 = fmaf(w1, f1.x, a0); a1 = fmaf(w1, f1.y, a1);
        a0 = fmaf(w2, f2.x, a0); a1 = fmaf(w2, f2.y, a1);
        a0 = fmaf(w3, f3.x, a0); a1 = fmaf(w3, f3.y, a1);
    }
    float inv = 1.f / (s + 1e-16f);
    float2 bv = __ldg(&((const float2*)bias)[lane]);
    float o0 = fmaf(a0, inv, bv.x);
    float o1 = fmaf(a1, inv, bv.y);
    if (do_relu) { o0 = fmaxf(o0, 0.f); o1 = fmaxf(o1, 0.f); }
    ((float2*)(OUT + ((size_t)dst << 6)))[lane] = make_float2(o0, o1);
}

// ---------------- launch ---------------------------------------------------
extern "C" void kernel_launch(void* const* d_in, const int* in_sizes, int n_in,
                              void* d_out, int out_size)
{
    const float* x   = (const float*)d_in[0];
    const int*   ei  = (const int*)  d_in[1];
    const float* W1  = (const float*)d_in[2];
    const float* as1 = (const float*)d_in[3];
    const float* ad1 = (const float*)d_in[4];
    const float* b1  = (const float*)d_in[5];
    const float* W2  = (const float*)d_in[6];
    const float* as2 = (const float*)d_in[7];
    const float* ad2 = (const float*)d_in[8];
    const float* b2  = (const float*)d_in[9];
    float* out = (float*)d_out;

    const int* src = ei;
    const int* dst = ei + EE;

    __half2* pH16; float *pZ, *pAS, *pAD;
    cudaGetSymbolAddress((void**)&pH16, g_h16);
    cudaGetSymbolAddress((void**)&pZ,   g_z);
    cudaGetSymbolAddress((void**)&pAS,  g_as);
    cudaGetSymbolAddress((void**)&pAD,  g_ad);

    static cudaStream_t s2 = nullptr, s3 = nullptr;
    static cudaEvent_t evFork = nullptr, evJoin = nullptr, evScan = nullptr, evPad = nullptr;
    if (s2 == nullptr) {
        cudaStreamCreateWithFlags(&s2, cudaStreamNonBlocking);
        cudaStreamCreateWithFlags(&s3, cudaStreamNonBlocking);
        cudaEventCreateWithFlags(&evFork, cudaEventDisableTiming);
        cudaEventCreateWithFlags(&evJoin, cudaEventDisableTiming);
        cudaEventCreateWithFlags(&evScan, cudaEventDisableTiming);
        cudaEventCreateWithFlags(&evPad,  cudaEventDisableTiming);
    }

    // fork: gemm1 on s2 (depends only on x/W1)
    cudaEventRecord(evFork, 0);
    cudaStreamWaitEvent(s2, evFork, 0);
    gemm_att_k<<<(NN + 127) / 128, 256, 0, s2>>>(x, W1, as1, ad1, pH16, pAS, pAD);
    cudaEventRecord(evJoin, s2);

    // CSR build on main stream (counts/flags pre-zeroed: init + pad_k)
    hist_k<<<(EE / 4 + 255) / 256, 256>>>((const int4*)dst);
    scan_k<<<(NN + 1023) / 1024, 256>>>();
    cudaEventRecord(evScan, 0);

    // pad on s3, concurrent with scatter (disjoint CSR slots)
    cudaStreamWaitEvent(s3, evScan, 0);
    pad_k<<<(NN + 255) / 256, 256, 0, s3>>>();
    cudaEventRecord(evPad, s3);

    scatter_k<<<(EE / 4 + 255) / 256, 256>>>((const int4*)src, (const int4*)dst);

    // join all, then layer-1 aggregate
    cudaStreamWaitEvent(0, evJoin, 0);
    cudaStreamWaitEvent(0, evPad, 0);
    aggregate_k<<<(NN * 32 + 255) / 256, 256>>>(pH16, b1, pZ, 1);

    // layer 2 (sequential: gemm2 needs z)
    gemm_att_k<<<(NN + 127) / 128, 256>>>(pZ, W2, as2, ad2, pH16, pAS, pAD);
    aggregate_k<<<(NN * 32 + 255) / 256, 256>>>(pH16, b2, out, 0);
}

// round 12
// speedup vs baseline: 1.0007x; 1.0007x over previous
#include <cuda_runtime.h>
#include <cuda_fp16.h>
#include <math.h>

#define NN 100000
#define EE 1600000
#define DD 64
#define CSRCAP 2000000   // EE + 3*NN + slack (CSR padded to multiples of 4)

// ---------------- scratch (device globals; no allocation allowed) ----------
// Zero-initialized at module load; pad_k re-zeroes g_counts/g_flag each launch
// AFTER their last use, so every graph replay sees zeros.
__device__ __half2 g_h16[(size_t)(NN + 1) * 32]; // fp16 mirror of X@W; row NN stays 0 (sentinel)
__device__ float   g_z[(size_t)NN * DD];         // layer-1 output (fp32)
__device__ float   g_as[NN + 1];                 // [NN] = -1e38 sentinel
__device__ float   g_ad[NN];
__device__ int     g_counts[NN];
__device__ int     g_offs[NN + 1];
__device__ __align__(16) int g_rank[EE];         // edge rank within its dst bucket
__device__ __align__(16) int g_csr[CSRCAP];
__device__ int     g_flag[128];
__device__ int     g_aggv[128];
__device__ int     g_prefv[128];

// ---------------- packed f32x2 helpers -------------------------------------
__device__ __forceinline__ unsigned long long dup2(float v) {
    unsigned long long r;
    asm("mov.b64 %0, {%1, %1};" : "=l"(r) : "f"(v));
    return r;
}
__device__ __forceinline__ unsigned long long fma2(unsigned long long a,
                                                   unsigned long long b,
                                                   unsigned long long c) {
    unsigned long long d;
    asm("fma.rn.f32x2 %0, %1, %2, %3;" : "=l"(d) : "l"(a), "l"(b), "l"(c));
    return d;
}
__device__ __forceinline__ void unpack2(unsigned long long v, float& lo, float& hi) {
    asm("mov.b64 {%0, %1}, %2;" : "=f"(lo), "=f"(hi) : "l"(v));
}

// ---------------- hist: count + record per-edge rank -----------------------
__global__ void hist_k(const int4* __restrict__ dst4) {
    int i = blockIdx.x * blockDim.x + threadIdx.x;
    if (i < EE / 4) {
        int4 d = dst4[i];
        int4 r;
        r.x = atomicAdd(&g_counts[d.x], 1);
        r.y = atomicAdd(&g_counts[d.y], 1);
        r.z = atomicAdd(&g_counts[d.z], 1);
        r.w = atomicAdd(&g_counts[d.w], 1);
        *(int4*)&g_rank[i * 4] = r;
    }
}

// ---------------- fused scan, warp-parallel decoupled lookback -------------
__global__ void __launch_bounds__(256) scan_k() {
    __shared__ int warpSums[8];
    __shared__ int sPrefix;
    int b = blockIdx.x, t = threadIdx.x;
    int base = b * 1024 + t * 4;
    int c0 = (base + 0 < NN) ? ((g_counts[base + 0] + 3) & ~3) : 0;
    int c1 = (base + 1 < NN) ? ((g_counts[base + 1] + 3) & ~3) : 0;
    int c2 = (base + 2 < NN) ? ((g_counts[base + 2] + 3) & ~3) : 0;
    int c3 = (base + 3 < NN) ? ((g_counts[base + 3] + 3) & ~3) : 0;
    int tsum = c0 + c1 + c2 + c3;
    int lane = t & 31, wid = t >> 5;
    int v = tsum;
    #pragma unroll
    for (int d = 1; d < 32; d <<= 1) {
        int n = __shfl_up_sync(0xffffffffu, v, d);
        if (lane >= d) v += n;
    }
    if (lane == 31) warpSums[wid] = v;
    __syncthreads();
    if (wid == 0 && lane < 8) {
        int wv = warpSums[lane];
        #pragma unroll
        for (int d = 1; d < 8; d <<= 1) {
            int n = __shfl_up_sync(0xffu, wv, d);
            if (lane >= d) wv += n;
        }
        warpSums[lane] = wv;
    }
    __syncthreads();
    if (wid == 0) {
        int T = warpSums[7];
        if (b == 0) {
            if (lane == 0) {
                g_prefv[0] = T;
                __threadfence();
                *(volatile int*)&g_flag[0] = 2;
                sPrefix = 0;
            }
        } else {
            if (lane == 0) {
                g_aggv[b] = T;
                __threadfence();
                *(volatile int*)&g_flag[b] = 1;
            }
            int run = 0;
            int baseJ = b - 1;
            while (true) {
                int j = baseJ - lane;
                int f = (j >= 0) ? *(volatile int*)&g_flag[j] : 3;
                while (__any_sync(0xffffffffu, f == 0)) {
                    if (f == 0) f = *(volatile int*)&g_flag[j];
                }
                __threadfence();
                int val = 0;
                if (j >= 0) val = (f == 2) ? g_prefv[j] : g_aggv[j];
                unsigned m2 = __ballot_sync(0xffffffffu, (j >= 0) && (f == 2));
                int stopLane = m2 ? (__ffs(m2) - 1) : 32;
                int contrib = (lane <= stopLane && j >= 0) ? val : 0;
                #pragma unroll
                for (int o = 16; o > 0; o >>= 1)
                    contrib += __shfl_down_sync(0xffffffffu, contrib, o);
                contrib = __shfl_sync(0xffffffffu, contrib, 0);
                run += contrib;
                if (m2) break;
                baseJ -= 32;
            }
            if (lane == 0) {
                sPrefix = run;
                g_prefv[b] = run + T;
                __threadfence();
                *(volatile int*)&g_flag[b] = 2;
            }
        }
    }
    __syncthreads();
    int exc = v - tsum + (wid > 0 ? warpSums[wid - 1] : 0) + sPrefix;
    int e0 = exc, e1 = exc + c0, e2 = e1 + c1, e3 = e2 + c2;
    if (base + 0 < NN) g_offs[base + 0] = e0;
    if (base + 1 < NN) g_offs[base + 1] = e1;
    if (base + 2 < NN) g_offs[base + 2] = e2;
    if (base + 3 < NN) g_offs[base + 3] = e3;
    if (base + 0 == NN - 1) g_offs[NN] = e1;
    if (base + 1 == NN - 1) g_offs[NN] = e2;
    if (base + 2 == NN - 1) g_offs[NN] = e3;
    if (base + 3 == NN - 1) g_offs[NN] = e3 + c3;
}

// sentinels into <=3 padding slots per node; re-zero counts+flags for replay.
// Touches ONLY padding slots -> safe to run concurrently with scatter_k.
__global__ void pad_k() {
    int i = blockIdx.x * blockDim.x + threadIdx.x;
    if (i == 0) g_as[NN] = -1e38f;
    if (i < 128) g_flag[i] = 0;
    if (i < NN) {
        int c = g_counts[i];
        int start = g_offs[i] + c;
        int end = g_offs[i + 1];
        for (int k = start; k < end; k++) g_csr[k] = NN;
        g_counts[i] = 0;
    }
}

// ---------------- scatter: NO atomics (rank precomputed) -------------------
__global__ void scatter_k(const int4* __restrict__ src4, const int4* __restrict__ dst4) {
    int i = blockIdx.x * blockDim.x + threadIdx.x;
    if (i < EE / 4) {
        int4 s = *(const int4*)&src4[i];
        int4 d = *(const int4*)&dst4[i];
        int4 r = *(const int4*)&g_rank[i * 4];
        g_csr[__ldg(&g_offs[d.x]) + r.x] = s.x;
        g_csr[__ldg(&g_offs[d.y]) + r.y] = s.y;
        g_csr[__ldg(&g_offs[d.z]) + r.z] = s.z;
        g_csr[__ldg(&g_offs[d.w]) + r.w] = s.w;
    }
}

// ---------------- dense: H16 = fp16(X@W), a_s, a_d -------------------------
// 256 threads, 128 rows x 64 cols per block, 8x4 outputs/thread, fma2.
__global__ void __launch_bounds__(256) gemm_att_k(
    const float* __restrict__ X, const float* __restrict__ W,
    const float* __restrict__ attS, const float* __restrict__ attD,
    __half2* __restrict__ H16, float* __restrict__ AS, float* __restrict__ AD)
{
    __shared__ float sW[64 * 64];        // [k][c]
    __shared__ float sXT[64 * 130];      // [k][r], 128 rows + pad
    __shared__ float sAtt[128];
    int tid = threadIdx.x;
    int rowBase = blockIdx.x * 128;

    #pragma unroll
    for (int i = 0; i < 4; i++)
        ((float4*)sW)[tid + 256 * i] = ((const float4*)W)[tid + 256 * i];
    if (tid < 128) sAtt[tid] = (tid < 64) ? attS[tid] : attD[tid - 64];

    {
        int r = tid >> 1;                 // 0..127
        int k0 = (tid & 1) * 32;          // 0 or 32
        int grow = rowBase + r;
        bool rv = grow < NN;
        const float4* xp = (const float4*)(X + (size_t)(rv ? grow : 0) * 64) + (k0 >> 2);
        #pragma unroll
        for (int i = 0; i < 8; i++) {
            float4 v = rv ? xp[i] : make_float4(0.f, 0.f, 0.f, 0.f);
            int kb = k0 + 4 * i;
            sXT[(kb + 0) * 130 + r] = v.x;
            sXT[(kb + 1) * 130 + r] = v.y;
            sXT[(kb + 2) * 130 + r] = v.z;
            sXT[(kb + 3) * 130 + r] = v.w;
        }
    }
    __syncthreads();

    int cg = (tid & 15) * 4;      // 16 col groups x 4 cols
    int rg = (tid >> 4) * 8;      // 16 row groups x 8 rows

    unsigned long long acc[4][4];
    #pragma unroll
    for (int a = 0; a < 4; a++)
        #pragma unroll
        for (int b = 0; b < 4; b++) acc[a][b] = 0ull;

    #pragma unroll 2
    for (int k = 0; k < 64; k++) {
        const float* xb = &sXT[k * 130 + rg];
        unsigned long long x01 = *(const unsigned long long*)(xb);
        unsigned long long x23 = *(const unsigned long long*)(xb + 2);
        unsigned long long x45 = *(const unsigned long long*)(xb + 4);
        unsigned long long x67 = *(const unsigned long long*)(xb + 6);
        float4 wv = *(const float4*)(&sW[(k << 6) + cg]);
        unsigned long long w0 = dup2(wv.x), w1 = dup2(wv.y);
        unsigned long long w2 = dup2(wv.z), w3 = dup2(wv.w);
        acc[0][0] = fma2(x01, w0, acc[0][0]);
        acc[0][1] = fma2(x01, w1, acc[0][1]);
        acc[0][2] = fma2(x01, w2, acc[0][2]);
        acc[0][3] = fma2(x01, w3, acc[0][3]);
        acc[1][0] = fma2(x23, w0, acc[1][0]);
        acc[1][1] = fma2(x23, w1, acc[1][1]);
        acc[1][2] = fma2(x23, w2, acc[1][2]);
        acc[1][3] = fma2(x23, w3, acc[1][3]);
        acc[2][0] = fma2(x45, w0, acc[2][0]);
        acc[2][1] = fma2(x45, w1, acc[2][1]);
        acc[2][2] = fma2(x45, w2, acc[2][2]);
        acc[2][3] = fma2(x45, w3, acc[2][3]);
        acc[3][0] = fma2(x67, w0, acc[3][0]);
        acc[3][1] = fma2(x67, w1, acc[3][1]);
        acc[3][2] = fma2(x67, w2, acc[3][2]);
        acc[3][3] = fma2(x67, w3, acc[3][3]);
    }

    float hv[8][4];
    #pragma unroll
    for (int rp = 0; rp < 4; rp++)
        #pragma unroll
        for (int c = 0; c < 4; c++)
            unpack2(acc[rp][c], hv[2 * rp][c], hv[2 * rp + 1][c]);

    float pas[8], pad_[8];
    #pragma unroll
    for (int r = 0; r < 8; r++) {
        float s = 0.f, d = 0.f;
        #pragma unroll
        for (int c = 0; c < 4; c++) {
            s = fmaf(hv[r][c], sAtt[cg + c], s);
            d = fmaf(hv[r][c], sAtt[64 + cg + c], d);
        }
        pas[r] = s; pad_[r] = d;
    }
    #pragma unroll
    for (int off = 8; off >= 1; off >>= 1) {
        #pragma unroll
        for (int r = 0; r < 8; r++) {
            pas[r]  += __shfl_xor_sync(0xffffffffu, pas[r],  off, 16);
            pad_[r] += __shfl_xor_sync(0xffffffffu, pad_[r], off, 16);
        }
    }
    if ((tid & 15) == 0) {
        #pragma unroll
        for (int r = 0; r < 8; r++) {
            int grow = rowBase + rg + r;
            if (grow < NN) { AS[grow] = pas[r]; AD[grow] = pad_[r]; }
        }
    }
    #pragma unroll
    for (int r = 0; r < 8; r++) {
        int grow = rowBase + rg + r;
        if (grow < NN) {
            union { __half2 h[2]; uint2 u; } cv;
            cv.h[0] = __floats2half2_rn(hv[r][0], hv[r][1]);
            cv.h[1] = __floats2half2_rn(hv[r][2], hv[r][3]);
            *(uint2*)(H16 + (size_t)grow * 32 + (cg >> 1)) = cv.u;
        }
    }
}

// ---------------- sparse aggregate: warp per dst, simple 4-edge loop -------
// Natural register count (~40) -- forcing occupancy caused spills (R11).
__global__ void __launch_bounds__(256) aggregate_k(
    const __half2* __restrict__ H16,
    const float* __restrict__ bias,
    float* __restrict__ OUT, int do_relu)
{
    int dst = (blockIdx.x * blockDim.x + threadIdx.x) >> 5;
    int lane = threadIdx.x & 31;
    if (dst >= NN) return;
    int j0 = __ldg(&g_offs[dst]);
    int j1 = __ldg(&g_offs[dst + 1]);
    float ad = __ldg(&g_ad[dst]);
    float s = 0.f, a0 = 0.f, a1 = 0.f;

    for (int j = j0; j < j1; j += 4) {
        int4 i4 = *(const int4*)&g_csr[j];          // uniform LDG.128
        float e0 = __ldg(&g_as[i4.x]) + ad;
        float e1 = __ldg(&g_as[i4.y]) + ad;
        float e2 = __ldg(&g_as[i4.z]) + ad;
        float e3 = __ldg(&g_as[i4.w]) + ad;
        __half2 v0 = __ldg(H16 + ((size_t)i4.x << 5) + lane);
        __half2 v1 = __ldg(H16 + ((size_t)i4.y << 5) + lane);
        __half2 v2 = __ldg(H16 + ((size_t)i4.z << 5) + lane);
        __half2 v3 = __ldg(H16 + ((size_t)i4.w << 5) + lane);
        e0 = e0 > 0.f ? e0 : 0.2f * e0;
        e1 = e1 > 0.f ? e1 : 0.2f * e1;
        e2 = e2 > 0.f ? e2 : 0.2f * e2;
        e3 = e3 > 0.f ? e3 : 0.2f * e3;
        float w0 = __expf(fminf(e0, 70.f));   // sentinel edges -> w=0
        float w1 = __expf(fminf(e1, 70.f));
        float w2 = __expf(fminf(e2, 70.f));
        float w3 = __expf(fminf(e3, 70.f));
        s += (w0 + w1) + (w2 + w3);
        float2 f0 = __half22float2(v0);
        float2 f1 = __half22float2(v1);
        float2 f2 = __half22float2(v2);
        float2 f3 = __half22float2(v3);
        a0 = fmaf(w0, f0.x, a0); a1 = fmaf(w0, f0.y, a1);
        a0 = fmaf(w1, f1.x, a0); a1 = fmaf(w1, f1.y, a1);
        a0 = fmaf(w2, f2.x, a0); a1 = fmaf(w2, f2.y, a1);
        a0 = fmaf(w3, f3.x, a0); a1 = fmaf(w3, f3.y, a1);
    }
    float inv = 1.f / (s + 1e-16f);
    float2 bv = __ldg(&((const float2*)bias)[lane]);
    float o0 = fmaf(a0, inv, bv.x);
    float o1 = fmaf(a1, inv, bv.y);
    if (do_relu) { o0 = fmaxf(o0, 0.f); o1 = fmaxf(o1, 0.f); }
    ((float2*)(OUT + ((size_t)dst << 6)))[lane] = make_float2(o0, o1);
}

// ---------------- launch ---------------------------------------------------
extern "C" void kernel_launch(void* const* d_in, const int* in_sizes, int n_in,
                              void* d_out, int out_size)
{
    const float* x   = (const float*)d_in[0];
    const int*   ei  = (const int*)  d_in[1];
    const float* W1  = (const float*)d_in[2];
    const float* as1 = (const float*)d_in[3];
    const float* ad1 = (const float*)d_in[4];
    const float* b1  = (const float*)d_in[5];
    const float* W2  = (const float*)d_in[6];
    const float* as2 = (const float*)d_in[7];
    const float* ad2 = (const float*)d_in[8];
    const float* b2  = (const float*)d_in[9];
    float* out = (float*)d_out;

    const int* src = ei;
    const int* dst = ei + EE;

    __half2* pH16; float *pZ, *pAS, *pAD;
    cudaGetSymbolAddress((void**)&pH16, g_h16);
    cudaGetSymbolAddress((void**)&pZ,   g_z);
    cudaGetSymbolAddress((void**)&pAS,  g_as);
    cudaGetSymbolAddress((void**)&pAD,  g_ad);

    static cudaStream_t s2 = nullptr, s3 = nullptr;
    static cudaEvent_t evFork = nullptr, evJoin = nullptr, evScan = nullptr, evPad = nullptr;
    if (s2 == nullptr) {
        cudaStreamCreateWithFlags(&s2, cudaStreamNonBlocking);
        cudaStreamCreateWithFlags(&s3, cudaStreamNonBlocking);
        cudaEventCreateWithFlags(&evFork, cudaEventDisableTiming);
        cudaEventCreateWithFlags(&evJoin, cudaEventDisableTiming);
        cudaEventCreateWithFlags(&evScan, cudaEventDisableTiming);
        cudaEventCreateWithFlags(&evPad,  cudaEventDisableTiming);
    }

    // fork: gemm1 on s2 (depends only on x/W1)
    cudaEventRecord(evFork, 0);
    cudaStreamWaitEvent(s2, evFork, 0);
    gemm_att_k<<<(NN + 127) / 128, 256, 0, s2>>>(x, W1, as1, ad1, pH16, pAS, pAD);
    cudaEventRecord(evJoin, s2);

    // CSR build on main stream (counts/flags pre-zeroed: init + pad_k)
    hist_k<<<(EE / 4 + 255) / 256, 256>>>((const int4*)dst);
    scan_k<<<(NN + 1023) / 1024, 256>>>();
    cudaEventRecord(evScan, 0);

    // pad on s3, concurrent with scatter (disjoint CSR slots)
    cudaStreamWaitEvent(s3, evScan, 0);
    pad_k<<<(NN + 255) / 256, 256, 0, s3>>>();
    cudaEventRecord(evPad, s3);

    scatter_k<<<(EE / 4 + 255) / 256, 256>>>((const int4*)src, (const int4*)dst);

    // join all, then layer-1 aggregate
    cudaStreamWaitEvent(0, evJoin, 0);
    cudaStreamWaitEvent(0, evPad, 0);
    aggregate_k<<<(NN * 32 + 255) / 256, 256>>>(pH16, b1, pZ, 1);

    // layer 2 (sequential: gemm2 needs z)
    gemm_att_k<<<(NN + 127) / 128, 256>>>(pZ, W2, as2, ad2, pH16, pAS, pAD);
    aggregate_k<<<(NN * 32 + 255) / 256, 256>>>(pH16, b2, out, 0);
}

// round 13
// speedup vs baseline: 1.1185x; 1.1178x over previous
#include <cuda_runtime.h>
#include <cuda_fp16.h>
#include <math.h>

#define NN 100000
#define EE 1600000
#define DD 64
#define CSRCAP 2000000   // EE + 3*NN + slack (CSR padded to multiples of 4)

// ---------------- scratch (device globals; no allocation allowed) ----------
// Zero-initialized at module load; pad_k re-zeroes g_counts/g_flag each launch
// AFTER their last use, so every graph replay sees zeros.
__device__ __half2 g_h16[(size_t)(NN + 1) * 32]; // fp16 mirror of X@W; row NN stays 0 (sentinel)
__device__ float   g_z[(size_t)NN * DD];         // layer-1 output (fp32)
__device__ float   g_as[NN + 1];                 // [NN] = -1e38 sentinel
__device__ float   g_ad[NN];
__device__ int     g_counts[NN];
__device__ int     g_offs[NN + 1];
__device__ int     g_cursor[NN];
__device__ __align__(16) int g_csr[CSRCAP];
__device__ int     g_flag[128];
__device__ int     g_aggv[128];
__device__ int     g_prefv[128];

// ---------------- packed f32x2 helpers -------------------------------------
__device__ __forceinline__ unsigned long long dup2(float v) {
    unsigned long long r;
    asm("mov.b64 %0, {%1, %1};" : "=l"(r) : "f"(v));
    return r;
}
__device__ __forceinline__ unsigned long long fma2(unsigned long long a,
                                                   unsigned long long b,
                                                   unsigned long long c) {
    unsigned long long d;
    asm("fma.rn.f32x2 %0, %1, %2, %3;" : "=l"(d) : "l"(a), "l"(b), "l"(c));
    return d;
}
__device__ __forceinline__ void unpack2(unsigned long long v, float& lo, float& hi) {
    asm("mov.b64 {%0, %1}, %2;" : "=f"(lo), "=f"(hi) : "l"(v));
}

// ---------------- hist (REDG atomics, no return use) ------------------------
__global__ void hist_k(const int4* __restrict__ dst4) {
    int i = blockIdx.x * blockDim.x + threadIdx.x;
    if (i < EE / 4) {
        int4 d = dst4[i];
        atomicAdd(&g_counts[d.x], 1);
        atomicAdd(&g_counts[d.y], 1);
        atomicAdd(&g_counts[d.z], 1);
        atomicAdd(&g_counts[d.w], 1);
    }
}

// ---------------- fused scan, warp-parallel decoupled lookback -------------
__global__ void __launch_bounds__(256) scan_k() {
    __shared__ int warpSums[8];
    __shared__ int sPrefix;
    int b = blockIdx.x, t = threadIdx.x;
    int base = b * 1024 + t * 4;
    int c0 = (base + 0 < NN) ? ((g_counts[base + 0] + 3) & ~3) : 0;
    int c1 = (base + 1 < NN) ? ((g_counts[base + 1] + 3) & ~3) : 0;
    int c2 = (base + 2 < NN) ? ((g_counts[base + 2] + 3) & ~3) : 0;
    int c3 = (base + 3 < NN) ? ((g_counts[base + 3] + 3) & ~3) : 0;
    int tsum = c0 + c1 + c2 + c3;
    int lane = t & 31, wid = t >> 5;
    int v = tsum;
    #pragma unroll
    for (int d = 1; d < 32; d <<= 1) {
        int n = __shfl_up_sync(0xffffffffu, v, d);
        if (lane >= d) v += n;
    }
    if (lane == 31) warpSums[wid] = v;
    __syncthreads();
    if (wid == 0 && lane < 8) {
        int wv = warpSums[lane];
        #pragma unroll
        for (int d = 1; d < 8; d <<= 1) {
            int n = __shfl_up_sync(0xffu, wv, d);
            if (lane >= d) wv += n;
        }
        warpSums[lane] = wv;
    }
    __syncthreads();
    if (wid == 0) {
        int T = warpSums[7];
        if (b == 0) {
            if (lane == 0) {
                g_prefv[0] = T;
                __threadfence();
                *(volatile int*)&g_flag[0] = 2;
                sPrefix = 0;
            }
        } else {
            if (lane == 0) {
                g_aggv[b] = T;
                __threadfence();
                *(volatile int*)&g_flag[b] = 1;
            }
            int run = 0;
            int baseJ = b - 1;
            while (true) {
                int j = baseJ - lane;
                int f = (j >= 0) ? *(volatile int*)&g_flag[j] : 3;
                while (__any_sync(0xffffffffu, f == 0)) {
                    if (f == 0) f = *(volatile int*)&g_flag[j];
                }
                __threadfence();
                int val = 0;
                if (j >= 0) val = (f == 2) ? g_prefv[j] : g_aggv[j];
                unsigned m2 = __ballot_sync(0xffffffffu, (j >= 0) && (f == 2));
                int stopLane = m2 ? (__ffs(m2) - 1) : 32;
                int contrib = (lane <= stopLane && j >= 0) ? val : 0;
                #pragma unroll
                for (int o = 16; o > 0; o >>= 1)
                    contrib += __shfl_down_sync(0xffffffffu, contrib, o);
                contrib = __shfl_sync(0xffffffffu, contrib, 0);
                run += contrib;
                if (m2) break;
                baseJ -= 32;
            }
            if (lane == 0) {
                sPrefix = run;
                g_prefv[b] = run + T;
                __threadfence();
                *(volatile int*)&g_flag[b] = 2;
            }
        }
    }
    __syncthreads();
    int exc = v - tsum + (wid > 0 ? warpSums[wid - 1] : 0) + sPrefix;
    int e0 = exc, e1 = exc + c0, e2 = e1 + c1, e3 = e2 + c2;
    if (base + 0 < NN) { g_offs[base + 0] = e0; g_cursor[base + 0] = e0; }
    if (base + 1 < NN) { g_offs[base + 1] = e1; g_cursor[base + 1] = e1; }
    if (base + 2 < NN) { g_offs[base + 2] = e2; g_cursor[base + 2] = e2; }
    if (base + 3 < NN) { g_offs[base + 3] = e3; g_cursor[base + 3] = e3; }
    if (base + 0 == NN - 1) g_offs[NN] = e1;
    if (base + 1 == NN - 1) g_offs[NN] = e2;
    if (base + 2 == NN - 1) g_offs[NN] = e3;
    if (base + 3 == NN - 1) g_offs[NN] = e3 + c3;
}

// sentinels into <=3 padding slots per node; re-zero counts+flags for replay
__global__ void pad_k() {
    int i = blockIdx.x * blockDim.x + threadIdx.x;
    if (i == 0) g_as[NN] = -1e38f;
    if (i < 128) g_flag[i] = 0;
    if (i < NN) {
        int c = g_counts[i];
        int start = g_offs[i] + c;
        int end = g_offs[i + 1];
        for (int k = start; k < end; k++) g_csr[k] = NN;
        g_counts[i] = 0;
    }
}

__global__ void scatter_k(const int4* __restrict__ src4, const int4* __restrict__ dst4) {
    int i = blockIdx.x * blockDim.x + threadIdx.x;
    if (i < EE / 4) {
        int4 s = src4[i];
        int4 d = dst4[i];
        g_csr[atomicAdd(&g_cursor[d.x], 1)] = s.x;
        g_csr[atomicAdd(&g_cursor[d.y], 1)] = s.y;
        g_csr[atomicAdd(&g_cursor[d.z], 1)] = s.z;
        g_csr[atomicAdd(&g_cursor[d.w], 1)] = s.w;
    }
}

// ---------------- dense: H16 = fp16(X@W), a_s, a_d -------------------------
// 256 threads, 128 rows x 64 cols per block, 8x4 outputs/thread, fma2.
__global__ void __launch_bounds__(256) gemm_att_k(
    const float* __restrict__ X, const float* __restrict__ W,
    const float* __restrict__ attS, const float* __restrict__ attD,
    __half2* __restrict__ H16, float* __restrict__ AS, float* __restrict__ AD)
{
    __shared__ float sW[64 * 64];        // [k][c]
    __shared__ float sXT[64 * 130];      // [k][r], 128 rows + pad
    __shared__ float sAtt[128];
    int tid = threadIdx.x;
    int rowBase = blockIdx.x * 128;

    #pragma unroll
    for (int i = 0; i < 4; i++)
        ((float4*)sW)[tid + 256 * i] = ((const float4*)W)[tid + 256 * i];
    if (tid < 128) sAtt[tid] = (tid < 64) ? attS[tid] : attD[tid - 64];

    {
        int r = tid >> 1;                 // 0..127
        int k0 = (tid & 1) * 32;          // 0 or 32
        int grow = rowBase + r;
        bool rv = grow < NN;
        const float4* xp = (const float4*)(X + (size_t)(rv ? grow : 0) * 64) + (k0 >> 2);
        #pragma unroll
        for (int i = 0; i < 8; i++) {
            float4 v = rv ? xp[i] : make_float4(0.f, 0.f, 0.f, 0.f);
            int kb = k0 + 4 * i;
            sXT[(kb + 0) * 130 + r] = v.x;
            sXT[(kb + 1) * 130 + r] = v.y;
            sXT[(kb + 2) * 130 + r] = v.z;
            sXT[(kb + 3) * 130 + r] = v.w;
        }
    }
    __syncthreads();

    int cg = (tid & 15) * 4;      // 16 col groups x 4 cols
    int rg = (tid >> 4) * 8;      // 16 row groups x 8 rows

    unsigned long long acc[4][4];
    #pragma unroll
    for (int a = 0; a < 4; a++)
        #pragma unroll
        for (int b = 0; b < 4; b++) acc[a][b] = 0ull;

    #pragma unroll 2
    for (int k = 0; k < 64; k++) {
        const float* xb = &sXT[k * 130 + rg];
        unsigned long long x01 = *(const unsigned long long*)(xb);
        unsigned long long x23 = *(const unsigned long long*)(xb + 2);
        unsigned long long x45 = *(const unsigned long long*)(xb + 4);
        unsigned long long x67 = *(const unsigned long long*)(xb + 6);
        float4 wv = *(const float4*)(&sW[(k << 6) + cg]);
        unsigned long long w0 = dup2(wv.x), w1 = dup2(wv.y);
        unsigned long long w2 = dup2(wv.z), w3 = dup2(wv.w);
        acc[0][0] = fma2(x01, w0, acc[0][0]);
        acc[0][1] = fma2(x01, w1, acc[0][1]);
        acc[0][2] = fma2(x01, w2, acc[0][2]);
        acc[0][3] = fma2(x01, w3, acc[0][3]);
        acc[1][0] = fma2(x23, w0, acc[1][0]);
        acc[1][1] = fma2(x23, w1, acc[1][1]);
        acc[1][2] = fma2(x23, w2, acc[1][2]);
        acc[1][3] = fma2(x23, w3, acc[1][3]);
        acc[2][0] = fma2(x45, w0, acc[2][0]);
        acc[2][1] = fma2(x45, w1, acc[2][1]);
        acc[2][2] = fma2(x45, w2, acc[2][2]);
        acc[2][3] = fma2(x45, w3, acc[2][3]);
        acc[3][0] = fma2(x67, w0, acc[3][0]);
        acc[3][1] = fma2(x67, w1, acc[3][1]);
        acc[3][2] = fma2(x67, w2, acc[3][2]);
        acc[3][3] = fma2(x67, w3, acc[3][3]);
    }

    float hv[8][4];
    #pragma unroll
    for (int rp = 0; rp < 4; rp++)
        #pragma unroll
        for (int c = 0; c < 4; c++)
            unpack2(acc[rp][c], hv[2 * rp][c], hv[2 * rp + 1][c]);

    float pas[8], pad_[8];
    #pragma unroll
    for (int r = 0; r < 8; r++) {
        float s = 0.f, d = 0.f;
        #pragma unroll
        for (int c = 0; c < 4; c++) {
            s = fmaf(hv[r][c], sAtt[cg + c], s);
            d = fmaf(hv[r][c], sAtt[64 + cg + c], d);
        }
        pas[r] = s; pad_[r] = d;
    }
    #pragma unroll
    for (int off = 8; off >= 1; off >>= 1) {
        #pragma unroll
        for (int r = 0; r < 8; r++) {
            pas[r]  += __shfl_xor_sync(0xffffffffu, pas[r],  off, 16);
            pad_[r] += __shfl_xor_sync(0xffffffffu, pad_[r], off, 16);
        }
    }
    if ((tid & 15) == 0) {
        #pragma unroll
        for (int r = 0; r < 8; r++) {
            int grow = rowBase + rg + r;
            if (grow < NN) { AS[grow] = pas[r]; AD[grow] = pad_[r]; }
        }
    }
    #pragma unroll
    for (int r = 0; r < 8; r++) {
        int grow = rowBase + rg + r;
        if (grow < NN) {
            union { __half2 h[2]; uint2 u; } cv;
            cv.h[0] = __floats2half2_rn(hv[r][0], hv[r][1]);
            cv.h[1] = __floats2half2_rn(hv[r][2], hv[r][3]);
            *(uint2*)(H16 + (size_t)grow * 32 + (cg >> 1)) = cv.u;
        }
    }
}

// ---------------- sparse aggregate: half-warp split per dst ----------------
// Two 16-lane halves of a warp process alternating 4-edge groups of the SAME
// dst; each lane covers 4 cols via one uint2 load; combine via shfl_xor(16).
__global__ void __launch_bounds__(256) aggregate_k(
    const __half2* __restrict__ H16,
    const float* __restrict__ bias,
    float* __restrict__ OUT, int do_relu)
{
    int dst = (blockIdx.x * blockDim.x + threadIdx.x) >> 5;
    int lane = threadIdx.x & 31;
    if (dst >= NN) return;
    int half = lane >> 4;        // 0 or 1
    int gl = lane & 15;          // covers cols [4*gl, 4*gl+4)
    int j0 = __ldg(&g_offs[dst]);
    int j1 = __ldg(&g_offs[dst + 1]);
    float ad = __ldg(&g_ad[dst]);
    float s = 0.f, a0 = 0.f, a1 = 0.f, a2 = 0.f, a3 = 0.f;

    for (int jA = j0; jA < j1; jA += 8) {
        int jSelf = jA + (half << 2);
        float vm = (jSelf < j1) ? 1.f : 0.f;
        int jc = (jSelf < j1) ? jSelf : j0;
        int4 i4 = *(const int4*)&g_csr[jc];          // one LDG, 2 reqs (per half)
        float e0 = __ldg(&g_as[i4.x]) + ad;
        float e1 = __ldg(&g_as[i4.y]) + ad;
        float e2 = __ldg(&g_as[i4.z]) + ad;
        float e3 = __ldg(&g_as[i4.w]) + ad;
        uint2 v0 = __ldg(&((const uint2*)(H16 + ((size_t)i4.x << 5)))[gl]);
        uint2 v1 = __ldg(&((const uint2*)(H16 + ((size_t)i4.y << 5)))[gl]);
        uint2 v2 = __ldg(&((const uint2*)(H16 + ((size_t)i4.z << 5)))[gl]);
        uint2 v3 = __ldg(&((const uint2*)(H16 + ((size_t)i4.w << 5)))[gl]);
        e0 = e0 > 0.f ? e0 : 0.2f * e0;
        e1 = e1 > 0.f ? e1 : 0.2f * e1;
        e2 = e2 > 0.f ? e2 : 0.2f * e2;
        e3 = e3 > 0.f ? e3 : 0.2f * e3;
        float w0 = __expf(fminf(e0, 70.f)) * vm;     // sentinel/invalid -> 0
        float w1 = __expf(fminf(e1, 70.f)) * vm;
        float w2 = __expf(fminf(e2, 70.f)) * vm;
        float w3 = __expf(fminf(e3, 70.f)) * vm;
        s += (w0 + w1) + (w2 + w3);
        float2 f;
        f = __half22float2(*(__half2*)&v0.x); a0 = fmaf(w0, f.x, a0); a1 = fmaf(w0, f.y, a1);
        f = __half22float2(*(__half2*)&v0.y); a2 = fmaf(w0, f.x, a2); a3 = fmaf(w0, f.y, a3);
        f = __half22float2(*(__half2*)&v1.x); a0 = fmaf(w1, f.x, a0); a1 = fmaf(w1, f.y, a1);
        f = __half22float2(*(__half2*)&v1.y); a2 = fmaf(w1, f.x, a2); a3 = fmaf(w1, f.y, a3);
        f = __half22float2(*(__half2*)&v2.x); a0 = fmaf(w2, f.x, a0); a1 = fmaf(w2, f.y, a1);
        f = __half22float2(*(__half2*)&v2.y); a2 = fmaf(w2, f.x, a2); a3 = fmaf(w2, f.y, a3);
        f = __half22float2(*(__half2*)&v3.x); a0 = fmaf(w3, f.x, a0); a1 = fmaf(w3, f.y, a1);
        f = __half22float2(*(__half2*)&v3.y); a2 = fmaf(w3, f.x, a2); a3 = fmaf(w3, f.y, a3);
    }
    // combine the two halves (col layouts are identical)
    s  += __shfl_xor_sync(0xffffffffu, s,  16);
    a0 += __shfl_xor_sync(0xffffffffu, a0, 16);
    a1 += __shfl_xor_sync(0xffffffffu, a1, 16);
    a2 += __shfl_xor_sync(0xffffffffu, a2, 16);
    a3 += __shfl_xor_sync(0xffffffffu, a3, 16);
    if (half == 0) {
        float inv = 1.f / (s + 1e-16f);
        float4 bv = __ldg(&((const float4*)bias)[gl]);
        float4 o;
        o.x = fmaf(a0, inv, bv.x);
        o.y = fmaf(a1, inv, bv.y);
        o.z = fmaf(a2, inv, bv.z);
        o.w = fmaf(a3, inv, bv.w);
        if (do_relu) {
            o.x = fmaxf(o.x, 0.f); o.y = fmaxf(o.y, 0.f);
            o.z = fmaxf(o.z, 0.f); o.w = fmaxf(o.w, 0.f);
        }
        ((float4*)(OUT + ((size_t)dst << 6)))[gl] = o;
    }
}

// ---------------- launch ---------------------------------------------------
extern "C" void kernel_launch(void* const* d_in, const int* in_sizes, int n_in,
                              void* d_out, int out_size)
{
    const float* x   = (const float*)d_in[0];
    const int*   ei  = (const int*)  d_in[1];
    const float* W1  = (const float*)d_in[2];
    const float* as1 = (const float*)d_in[3];
    const float* ad1 = (const float*)d_in[4];
    const float* b1  = (const float*)d_in[5];
    const float* W2  = (const float*)d_in[6];
    const float* as2 = (const float*)d_in[7];
    const float* ad2 = (const float*)d_in[8];
    const float* b2  = (const float*)d_in[9];
    float* out = (float*)d_out;

    const int* src = ei;
    const int* dst = ei + EE;

    __half2* pH16; float *pZ, *pAS, *pAD;
    cudaGetSymbolAddress((void**)&pH16, g_h16);
    cudaGetSymbolAddress((void**)&pZ,   g_z);
    cudaGetSymbolAddress((void**)&pAS,  g_as);
    cudaGetSymbolAddress((void**)&pAD,  g_ad);

    static cudaStream_t s2 = nullptr;
    static cudaEvent_t evFork = nullptr, evJoin = nullptr;
    if (s2 == nullptr) {
        cudaStreamCreateWithFlags(&s2, cudaStreamNonBlocking);
        cudaEventCreateWithFlags(&evFork, cudaEventDisableTiming);
        cudaEventCreateWithFlags(&evJoin, cudaEventDisableTiming);
    }

    // fork: gemm1 on s2 (depends only on x/W1)
    cudaEventRecord(evFork, 0);
    cudaStreamWaitEvent(s2, evFork, 0);
    gemm_att_k<<<(NN + 127) / 128, 256, 0, s2>>>(x, W1, as1, ad1, pH16, pAS, pAD);
    cudaEventRecord(evJoin, s2);

    // CSR build on main stream (counts/flags pre-zeroed: init + pad_k)
    hist_k<<<(EE / 4 + 255) / 256, 256>>>((const int4*)dst);
    scan_k<<<(NN + 1023) / 1024, 256>>>();
    pad_k<<<(NN + 255) / 256, 256>>>();
    scatter_k<<<(EE / 4 + 255) / 256, 256>>>((const int4*)src, (const int4*)dst);

    // join, then layer-1 aggregate
    cudaStreamWaitEvent(0, evJoin, 0);
    aggregate_k<<<(NN * 32 + 255) / 256, 256>>>(pH16, b1, pZ, 1);

    // layer 2 (sequential: gemm2 needs z)
    gemm_att_k<<<(NN + 127) / 128, 256>>>(pZ, W2, as2, ad2, pH16, pAS, pAD);
    aggregate_k<<<(NN * 32 + 255) / 256, 256>>>(pH16, b2, out, 0);
}

// round 14
// speedup vs baseline: 1.1279x; 1.0083x over previous
#include <cuda_runtime.h>
#include <cuda_fp16.h>
#include <math.h>

#define NN 100000
#define EE 1600000
#define DD 64
#define CSRCAP 2000000   // EE + 3*NN + slack (CSR padded to multiples of 4)

// ---------------- scratch (device globals; no allocation allowed) ----------
// Zero-initialized at module load; pad_k re-zeroes g_counts/g_flag each launch
// AFTER their last use, so every graph replay sees zeros.
__device__ __half2 g_h16[(size_t)(NN + 1) * 32]; // fp16 mirror of X@W; row NN stays 0 (sentinel)
__device__ float   g_z[(size_t)NN * DD];         // layer-1 output (fp32)
__device__ float   g_as[NN + 1];                 // [NN] = -1e38 sentinel
__device__ float   g_ad[NN];
__device__ int     g_counts[NN];
__device__ int     g_offs[NN + 1];
__device__ int     g_cursor[NN];
__device__ __align__(16) int g_csr[CSRCAP];
__device__ int     g_flag[128];
__device__ int     g_aggv[128];
__device__ int     g_prefv[128];

// ---------------- packed f32x2 helpers -------------------------------------
__device__ __forceinline__ unsigned long long dup2(float v) {
    unsigned long long r;
    asm("mov.b64 %0, {%1, %1};" : "=l"(r) : "f"(v));
    return r;
}
__device__ __forceinline__ unsigned long long fma2(unsigned long long a,
                                                   unsigned long long b,
                                                   unsigned long long c) {
    unsigned long long d;
    asm("fma.rn.f32x2 %0, %1, %2, %3;" : "=l"(d) : "l"(a), "l"(b), "l"(c));
    return d;
}
__device__ __forceinline__ void unpack2(unsigned long long v, float& lo, float& hi) {
    asm("mov.b64 {%0, %1}, %2;" : "=f"(lo), "=f"(hi) : "l"(v));
}

// ---------------- hist (REDG atomics, no return use) ------------------------
__global__ void hist_k(const int4* __restrict__ dst4) {
    int i = blockIdx.x * blockDim.x + threadIdx.x;
    if (i < EE / 4) {
        int4 d = dst4[i];
        atomicAdd(&g_counts[d.x], 1);
        atomicAdd(&g_counts[d.y], 1);
        atomicAdd(&g_counts[d.z], 1);
        atomicAdd(&g_counts[d.w], 1);
    }
}

// ---------------- fused scan, warp-parallel decoupled lookback -------------
__global__ void __launch_bounds__(256) scan_k() {
    __shared__ int warpSums[8];
    __shared__ int sPrefix;
    int b = blockIdx.x, t = threadIdx.x;
    int base = b * 1024 + t * 4;
    int c0 = (base + 0 < NN) ? ((g_counts[base + 0] + 3) & ~3) : 0;
    int c1 = (base + 1 < NN) ? ((g_counts[base + 1] + 3) & ~3) : 0;
    int c2 = (base + 2 < NN) ? ((g_counts[base + 2] + 3) & ~3) : 0;
    int c3 = (base + 3 < NN) ? ((g_counts[base + 3] + 3) & ~3) : 0;
    int tsum = c0 + c1 + c2 + c3;
    int lane = t & 31, wid = t >> 5;
    int v = tsum;
    #pragma unroll
    for (int d = 1; d < 32; d <<= 1) {
        int n = __shfl_up_sync(0xffffffffu, v, d);
        if (lane >= d) v += n;
    }
    if (lane == 31) warpSums[wid] = v;
    __syncthreads();
    if (wid == 0 && lane < 8) {
        int wv = warpSums[lane];
        #pragma unroll
        for (int d = 1; d < 8; d <<= 1) {
            int n = __shfl_up_sync(0xffu, wv, d);
            if (lane >= d) wv += n;
        }
        warpSums[lane] = wv;
    }
    __syncthreads();
    if (wid == 0) {
        int T = warpSums[7];
        if (b == 0) {
            if (lane == 0) {
                g_prefv[0] = T;
                __threadfence();
                *(volatile int*)&g_flag[0] = 2;
                sPrefix = 0;
            }
        } else {
            if (lane == 0) {
                g_aggv[b] = T;
                __threadfence();
                *(volatile int*)&g_flag[b] = 1;
            }
            int run = 0;
            int baseJ = b - 1;
            while (true) {
                int j = baseJ - lane;
                int f = (j >= 0) ? *(volatile int*)&g_flag[j] : 3;
                while (__any_sync(0xffffffffu, f == 0)) {
                    if (f == 0) f = *(volatile int*)&g_flag[j];
                }
                __threadfence();
                int val = 0;
                if (j >= 0) val = (f == 2) ? g_prefv[j] : g_aggv[j];
                unsigned m2 = __ballot_sync(0xffffffffu, (j >= 0) && (f == 2));
                int stopLane = m2 ? (__ffs(m2) - 1) : 32;
                int contrib = (lane <= stopLane && j >= 0) ? val : 0;
                #pragma unroll
                for (int o = 16; o > 0; o >>= 1)
                    contrib += __shfl_down_sync(0xffffffffu, contrib, o);
                contrib = __shfl_sync(0xffffffffu, contrib, 0);
                run += contrib;
                if (m2) break;
                baseJ -= 32;
            }
            if (lane == 0) {
                sPrefix = run;
                g_prefv[b] = run + T;
                __threadfence();
                *(volatile int*)&g_flag[b] = 2;
            }
        }
    }
    __syncthreads();
    int exc = v - tsum + (wid > 0 ? warpSums[wid - 1] : 0) + sPrefix;
    int e0 = exc, e1 = exc + c0, e2 = e1 + c1, e3 = e2 + c2;
    if (base + 0 < NN) { g_offs[base + 0] = e0; g_cursor[base + 0] = e0; }
    if (base + 1 < NN) { g_offs[base + 1] = e1; g_cursor[base + 1] = e1; }
    if (base + 2 < NN) { g_offs[base + 2] = e2; g_cursor[base + 2] = e2; }
    if (base + 3 < NN) { g_offs[base + 3] = e3; g_cursor[base + 3] = e3; }
    if (base + 0 == NN - 1) g_offs[NN] = e1;
    if (base + 1 == NN - 1) g_offs[NN] = e2;
    if (base + 2 == NN - 1) g_offs[NN] = e3;
    if (base + 3 == NN - 1) g_offs[NN] = e3 + c3;
}

// sentinels into <=3 padding slots per node; re-zero counts+flags for replay
__global__ void pad_k() {
    int i = blockIdx.x * blockDim.x + threadIdx.x;
    if (i == 0) g_as[NN] = -1e38f;
    if (i < 128) g_flag[i] = 0;
    if (i < NN) {
        int c = g_counts[i];
        int start = g_offs[i] + c;
        int end = g_offs[i + 1];
        for (int k = start; k < end; k++) g_csr[k] = NN;
        g_counts[i] = 0;
    }
}

__global__ void scatter_k(const int4* __restrict__ src4, const int4* __restrict__ dst4) {
    int i = blockIdx.x * blockDim.x + threadIdx.x;
    if (i < EE / 4) {
        int4 s = src4[i];
        int4 d = dst4[i];
        g_csr[atomicAdd(&g_cursor[d.x], 1)] = s.x;
        g_csr[atomicAdd(&g_cursor[d.y], 1)] = s.y;
        g_csr[atomicAdd(&g_cursor[d.z], 1)] = s.z;
        g_csr[atomicAdd(&g_cursor[d.w], 1)] = s.w;
    }
}

// ---------------- dense: H16 = fp16(X@W), a_s, a_d -------------------------
// 256 threads, 128 rows x 64 cols per block, 8x4 outputs/thread, fma2.
__global__ void __launch_bounds__(256) gemm_att_k(
    const float* __restrict__ X, const float* __restrict__ W,
    const float* __restrict__ attS, const float* __restrict__ attD,
    __half2* __restrict__ H16, float* __restrict__ AS, float* __restrict__ AD)
{
    __shared__ float sW[64 * 64];        // [k][c]
    __shared__ float sXT[64 * 130];      // [k][r], 128 rows + pad
    __shared__ float sAtt[128];
    int tid = threadIdx.x;
    int rowBase = blockIdx.x * 128;

    #pragma unroll
    for (int i = 0; i < 4; i++)
        ((float4*)sW)[tid + 256 * i] = ((const float4*)W)[tid + 256 * i];
    if (tid < 128) sAtt[tid] = (tid < 64) ? attS[tid] : attD[tid - 64];

    {
        int r = tid >> 1;                 // 0..127
        int k0 = (tid & 1) * 32;          // 0 or 32
        int grow = rowBase + r;
        bool rv = grow < NN;
        const float4* xp = (const float4*)(X + (size_t)(rv ? grow : 0) * 64) + (k0 >> 2);
        #pragma unroll
        for (int i = 0; i < 8; i++) {
            float4 v = rv ? xp[i] : make_float4(0.f, 0.f, 0.f, 0.f);
            int kb = k0 + 4 * i;
            sXT[(kb + 0) * 130 + r] = v.x;
            sXT[(kb + 1) * 130 + r] = v.y;
            sXT[(kb + 2) * 130 + r] = v.z;
            sXT[(kb + 3) * 130 + r] = v.w;
        }
    }
    __syncthreads();

    int cg = (tid & 15) * 4;      // 16 col groups x 4 cols
    int rg = (tid >> 4) * 8;      // 16 row groups x 8 rows

    unsigned long long acc[4][4];
    #pragma unroll
    for (int a = 0; a < 4; a++)
        #pragma unroll
        for (int b = 0; b < 4; b++) acc[a][b] = 0ull;

    #pragma unroll 2
    for (int k = 0; k < 64; k++) {
        const float* xb = &sXT[k * 130 + rg];
        unsigned long long x01 = *(const unsigned long long*)(xb);
        unsigned long long x23 = *(const unsigned long long*)(xb + 2);
        unsigned long long x45 = *(const unsigned long long*)(xb + 4);
        unsigned long long x67 = *(const unsigned long long*)(xb + 6);
        float4 wv = *(const float4*)(&sW[(k << 6) + cg]);
        unsigned long long w0 = dup2(wv.x), w1 = dup2(wv.y);
        unsigned long long w2 = dup2(wv.z), w3 = dup2(wv.w);
        acc[0][0] = fma2(x01, w0, acc[0][0]);
        acc[0][1] = fma2(x01, w1, acc[0][1]);
        acc[0][2] = fma2(x01, w2, acc[0][2]);
        acc[0][3] = fma2(x01, w3, acc[0][3]);
        acc[1][0] = fma2(x23, w0, acc[1][0]);
        acc[1][1] = fma2(x23, w1, acc[1][1]);
        acc[1][2] = fma2(x23, w2, acc[1][2]);
        acc[1][3] = fma2(x23, w3, acc[1][3]);
        acc[2][0] = fma2(x45, w0, acc[2][0]);
        acc[2][1] = fma2(x45, w1, acc[2][1]);
        acc[2][2] = fma2(x45, w2, acc[2][2]);
        acc[2][3] = fma2(x45, w3, acc[2][3]);
        acc[3][0] = fma2(x67, w0, acc[3][0]);
        acc[3][1] = fma2(x67, w1, acc[3][1]);
        acc[3][2] = fma2(x67, w2, acc[3][2]);
        acc[3][3] = fma2(x67, w3, acc[3][3]);
    }

    float hv[8][4];
    #pragma unroll
    for (int rp = 0; rp < 4; rp++)
        #pragma unroll
        for (int c = 0; c < 4; c++)
            unpack2(acc[rp][c], hv[2 * rp][c], hv[2 * rp + 1][c]);

    float pas[8], pad_[8];
    #pragma unroll
    for (int r = 0; r < 8; r++) {
        float s = 0.f, d = 0.f;
        #pragma unroll
        for (int c = 0; c < 4; c++) {
            s = fmaf(hv[r][c], sAtt[cg + c], s);
            d = fmaf(hv[r][c], sAtt[64 + cg + c], d);
        }
        pas[r] = s; pad_[r] = d;
    }
    #pragma unroll
    for (int off = 8; off >= 1; off >>= 1) {
        #pragma unroll
        for (int r = 0; r < 8; r++) {
            pas[r]  += __shfl_xor_sync(0xffffffffu, pas[r],  off, 16);
            pad_[r] += __shfl_xor_sync(0xffffffffu, pad_[r], off, 16);
        }
    }
    if ((tid & 15) == 0) {
        #pragma unroll
        for (int r = 0; r < 8; r++) {
            int grow = rowBase + rg + r;
            if (grow < NN) { AS[grow] = pas[r]; AD[grow] = pad_[r]; }
        }
    }
    #pragma unroll
    for (int r = 0; r < 8; r++) {
        int grow = rowBase + rg + r;
        if (grow < NN) {
            union { __half2 h[2]; uint2 u; } cv;
            cv.h[0] = __floats2half2_rn(hv[r][0], hv[r][1]);
            cv.h[1] = __floats2half2_rn(hv[r][2], hv[r][3]);
            *(uint2*)(H16 + (size_t)grow * 32 + (cg >> 1)) = cv.u;
        }
    }
}

// ---------------- sparse aggregate: quarter-warp split per dst -------------
// Four 8-lane groups of a warp process alternating 4-edge slots of the SAME
// dst; each lane covers 8 cols via one uint4 load; combine via shfl_xor(8,16).
__global__ void __launch_bounds__(256) aggregate_k(
    const __half2* __restrict__ H16,
    const float* __restrict__ bias,
    float* __restrict__ OUT, int do_relu)
{
    int dst = (blockIdx.x * blockDim.x + threadIdx.x) >> 5;
    int lane = threadIdx.x & 31;
    if (dst >= NN) return;
    int grp = lane >> 3;         // 0..3
    int gl = lane & 7;           // covers cols [8*gl, 8*gl+8)
    int j0 = __ldg(&g_offs[dst]);
    int j1 = __ldg(&g_offs[dst + 1]);
    float ad = __ldg(&g_ad[dst]);
    float s = 0.f;
    float a0 = 0.f, a1 = 0.f, a2 = 0.f, a3 = 0.f;
    float a4 = 0.f, a5 = 0.f, a6 = 0.f, a7 = 0.f;

    for (int jA = j0; jA < j1; jA += 16) {
        int jSelf = jA + (grp << 2);
        float vm = (jSelf < j1) ? 1.f : 0.f;
        int jc = (jSelf < j1) ? jSelf : j0;
        int4 i4 = *(const int4*)&g_csr[jc];
        float e0 = __ldg(&g_as[i4.x]) + ad;
        float e1 = __ldg(&g_as[i4.y]) + ad;
        float e2 = __ldg(&g_as[i4.z]) + ad;
        float e3 = __ldg(&g_as[i4.w]) + ad;
        uint4 v0 = __ldg(&((const uint4*)(H16 + ((size_t)i4.x << 5)))[gl]);
        uint4 v1 = __ldg(&((const uint4*)(H16 + ((size_t)i4.y << 5)))[gl]);
        uint4 v2 = __ldg(&((const uint4*)(H16 + ((size_t)i4.z << 5)))[gl]);
        uint4 v3 = __ldg(&((const uint4*)(H16 + ((size_t)i4.w << 5)))[gl]);
        e0 = e0 > 0.f ? e0 : 0.2f * e0;
        e1 = e1 > 0.f ? e1 : 0.2f * e1;
        e2 = e2 > 0.f ? e2 : 0.2f * e2;
        e3 = e3 > 0.f ? e3 : 0.2f * e3;
        float w0 = __expf(fminf(e0, 70.f)) * vm;     // sentinel/invalid -> 0
        float w1 = __expf(fminf(e1, 70.f)) * vm;
        float w2 = __expf(fminf(e2, 70.f)) * vm;
        float w3 = __expf(fminf(e3, 70.f)) * vm;
        s += (w0 + w1) + (w2 + w3);
        float2 f;
        f = __half22float2(*(__half2*)&v0.x); a0 = fmaf(w0, f.x, a0); a1 = fmaf(w0, f.y, a1);
        f = __half22float2(*(__half2*)&v0.y); a2 = fmaf(w0, f.x, a2); a3 = fmaf(w0, f.y, a3);
        f = __half22float2(*(__half2*)&v0.z); a4 = fmaf(w0, f.x, a4); a5 = fmaf(w0, f.y, a5);
        f = __half22float2(*(__half2*)&v0.w); a6 = fmaf(w0, f.x, a6); a7 = fmaf(w0, f.y, a7);
        f = __half22float2(*(__half2*)&v1.x); a0 = fmaf(w1, f.x, a0); a1 = fmaf(w1, f.y, a1);
        f = __half22float2(*(__half2*)&v1.y); a2 = fmaf(w1, f.x, a2); a3 = fmaf(w1, f.y, a3);
        f = __half22float2(*(__half2*)&v1.z); a4 = fmaf(w1, f.x, a4); a5 = fmaf(w1, f.y, a5);
        f = __half22float2(*(__half2*)&v1.w); a6 = fmaf(w1, f.x, a6); a7 = fmaf(w1, f.y, a7);
        f = __half22float2(*(__half2*)&v2.x); a0 = fmaf(w2, f.x, a0); a1 = fmaf(w2, f.y, a1);
        f = __half22float2(*(__half2*)&v2.y); a2 = fmaf(w2, f.x, a2); a3 = fmaf(w2, f.y, a3);
        f = __half22float2(*(__half2*)&v2.z); a4 = fmaf(w2, f.x, a4); a5 = fmaf(w2, f.y, a5);
        f = __half22float2(*(__half2*)&v2.w); a6 = fmaf(w2, f.x, a6); a7 = fmaf(w2, f.y, a7);
        f = __half22float2(*(__half2*)&v3.x); a0 = fmaf(w3, f.x, a0); a1 = fmaf(w3, f.y, a1);
        f = __half22float2(*(__half2*)&v3.y); a2 = fmaf(w3, f.x, a2); a3 = fmaf(w3, f.y, a3);
        f = __half22float2(*(__half2*)&v3.z); a4 = fmaf(w3, f.x, a4); a5 = fmaf(w3, f.y, a5);
        f = __half22float2(*(__half2*)&v3.w); a6 = fmaf(w3, f.x, a6); a7 = fmaf(w3, f.y, a7);
    }
    // combine the four groups (col layouts identical)
    #pragma unroll
    for (int off = 8; off <= 16; off <<= 1) {
        s  += __shfl_xor_sync(0xffffffffu, s,  off);
        a0 += __shfl_xor_sync(0xffffffffu, a0, off);
        a1 += __shfl_xor_sync(0xffffffffu, a1, off);
        a2 += __shfl_xor_sync(0xffffffffu, a2, off);
        a3 += __shfl_xor_sync(0xffffffffu, a3, off);
        a4 += __shfl_xor_sync(0xffffffffu, a4, off);
        a5 += __shfl_xor_sync(0xffffffffu, a5, off);
        a6 += __shfl_xor_sync(0xffffffffu, a6, off);
        a7 += __shfl_xor_sync(0xffffffffu, a7, off);
    }
    if (lane < 8) {
        float inv = 1.f / (s + 1e-16f);
        float4 b0 = __ldg(&((const float4*)bias)[2 * gl]);
        float4 b1 = __ldg(&((const float4*)bias)[2 * gl + 1]);
        float4 o0, o1;
        o0.x = fmaf(a0, inv, b0.x);
        o0.y = fmaf(a1, inv, b0.y);
        o0.z = fmaf(a2, inv, b0.z);
        o0.w = fmaf(a3, inv, b0.w);
        o1.x = fmaf(a4, inv, b1.x);
        o1.y = fmaf(a5, inv, b1.y);
        o1.z = fmaf(a6, inv, b1.z);
        o1.w = fmaf(a7, inv, b1.w);
        if (do_relu) {
            o0.x = fmaxf(o0.x, 0.f); o0.y = fmaxf(o0.y, 0.f);
            o0.z = fmaxf(o0.z, 0.f); o0.w = fmaxf(o0.w, 0.f);
            o1.x = fmaxf(o1.x, 0.f); o1.y = fmaxf(o1.y, 0.f);
            o1.z = fmaxf(o1.z, 0.f); o1.w = fmaxf(o1.w, 0.f);
        }
        float4* op = (float4*)(OUT + ((size_t)dst << 6));
        op[2 * gl] = o0;
        op[2 * gl + 1] = o1;
    }
}

// ---------------- launch ---------------------------------------------------
extern "C" void kernel_launch(void* const* d_in, const int* in_sizes, int n_in,
                              void* d_out, int out_size)
{
    const float* x   = (const float*)d_in[0];
    const int*   ei  = (const int*)  d_in[1];
    const float* W1  = (const float*)d_in[2];
    const float* as1 = (const float*)d_in[3];
    const float* ad1 = (const float*)d_in[4];
    const float* b1  = (const float*)d_in[5];
    const float* W2  = (const float*)d_in[6];
    const float* as2 = (const float*)d_in[7];
    const float* ad2 = (const float*)d_in[8];
    const float* b2  = (const float*)d_in[9];
    float* out = (float*)d_out;

    const int* src = ei;
    const int* dst = ei + EE;

    __half2* pH16; float *pZ, *pAS, *pAD;
    cudaGetSymbolAddress((void**)&pH16, g_h16);
    cudaGetSymbolAddress((void**)&pZ,   g_z);
    cudaGetSymbolAddress((void**)&pAS,  g_as);
    cudaGetSymbolAddress((void**)&pAD,  g_ad);

    static cudaStream_t s2 = nullptr;
    static cudaEvent_t evFork = nullptr, evJoin = nullptr;
    if (s2 == nullptr) {
        cudaStreamCreateWithFlags(&s2, cudaStreamNonBlocking);
        cudaEventCreateWithFlags(&evFork, cudaEventDisableTiming);
        cudaEventCreateWithFlags(&evJoin, cudaEventDisableTiming);
    }

    // fork: gemm1 on s2 (depends only on x/W1)
    cudaEventRecord(evFork, 0);
    cudaStreamWaitEvent(s2, evFork, 0);
    gemm_att_k<<<(NN + 127) / 128, 256, 0, s2>>>(x, W1, as1, ad1, pH16, pAS, pAD);
    cudaEventRecord(evJoin, s2);

    // CSR build on main stream (counts/flags pre-zeroed: init + pad_k)
    hist_k<<<(EE / 4 + 255) / 256, 256>>>((const int4*)dst);
    scan_k<<<(NN + 1023) / 1024, 256>>>();
    pad_k<<<(NN + 255) / 256, 256>>>();
    scatter_k<<<(EE / 4 + 255) / 256, 256>>>((const int4*)src, (const int4*)dst);

    // join, then layer-1 aggregate
    cudaStreamWaitEvent(0, evJoin, 0);
    aggregate_k<<<(NN * 32 + 255) / 256, 256>>>(pH16, b1, pZ, 1);

    // layer 2 (sequential: gemm2 needs z)
    gemm_att_k<<<(NN + 127) / 128, 256>>>(pZ, W2, as2, ad2, pH16, pAS, pAD);
    aggregate_k<<<(NN * 32 + 255) / 256, 256>>>(pH16, b2, out, 0);
}

// round 16
// speedup vs baseline: 1.1316x; 1.0033x over previous
#include <cuda_runtime.h>
#include <cuda_fp16.h>
#include <math.h>

#define NN 100000
#define EE 1600000
#define DD 64
#define CSRCAP 2000000   // EE + 3*NN + slack (CSR padded to multiples of 4)
#define CHUNK 50048      // layer-boundary pipeline split (multiple of 128)

// ---------------- scratch (device globals; no allocation allowed) ----------
// Zero-initialized at module load; pad_k re-zeroes g_counts/g_flag each launch
// AFTER their last use, so every graph replay sees zeros.
// DOUBLE-BUFFERED layer state: layer1 -> {h16a, as1, ad1}, layer2 -> {h16b, as2, ad2}
// so the layer-boundary pipeline has no cross-stream WAR race.
__device__ __half2 g_h16a[(size_t)(NN + 1) * 32]; // row NN stays 0 (sentinel)
__device__ __half2 g_h16b[(size_t)(NN + 1) * 32]; // row NN stays 0 (sentinel)
__device__ float   g_z[(size_t)NN * DD];          // layer-1 output (fp32)
__device__ float   g_as1[NN + 1];                 // [NN] = -1e38 sentinel
__device__ float   g_as2[NN + 1];                 // [NN] = -1e38 sentinel
__device__ float   g_ad1[NN];
__device__ float   g_ad2[NN];
__device__ int     g_counts[NN];
__device__ int     g_offs[NN + 1];
__device__ int     g_cursor[NN];
__device__ __align__(16) int g_csr[CSRCAP];
__device__ int     g_flag[128];
__device__ int     g_aggv[128];
__device__ int     g_prefv[128];

// ---------------- packed f32x2 helpers -------------------------------------
__device__ __forceinline__ unsigned long long dup2(float v) {
    unsigned long long r;
    asm("mov.b64 %0, {%1, %1};" : "=l"(r) : "f"(v));
    return r;
}
__device__ __forceinline__ unsigned long long fma2(unsigned long long a,
                                                   unsigned long long b,
                                                   unsigned long long c) {
    unsigned long long d;
    asm("fma.rn.f32x2 %0, %1, %2, %3;" : "=l"(d) : "l"(a), "l"(b), "l"(c));
    return d;
}
__device__ __forceinline__ void unpack2(unsigned long long v, float& lo, float& hi) {
    asm("mov.b64 {%0, %1}, %2;" : "=f"(lo), "=f"(hi) : "l"(v));
}

// ---------------- hist (REDG atomics, no return use) ------------------------
__global__ void hist_k(const int4* __restrict__ dst4) {
    int i = blockIdx.x * blockDim.x + threadIdx.x;
    if (i < EE / 4) {
        int4 d = dst4[i];
        atomicAdd(&g_counts[d.x], 1);
        atomicAdd(&g_counts[d.y], 1);
        atomicAdd(&g_counts[d.z], 1);
        atomicAdd(&g_counts[d.w], 1);
    }
}

// ---------------- fused scan, warp-parallel decoupled lookback -------------
__global__ void __launch_bounds__(256) scan_k() {
    __shared__ int warpSums[8];
    __shared__ int sPrefix;
    int b = blockIdx.x, t = threadIdx.x;
    int base = b * 1024 + t * 4;
    int c0 = (base + 0 < NN) ? ((g_counts[base + 0] + 3) & ~3) : 0;
    int c1 = (base + 1 < NN) ? ((g_counts[base + 1] + 3) & ~3) : 0;
    int c2 = (base + 2 < NN) ? ((g_counts[base + 2] + 3) & ~3) : 0;
    int c3 = (base + 3 < NN) ? ((g_counts[base + 3] + 3) & ~3) : 0;
    int tsum = c0 + c1 + c2 + c3;
    int lane = t & 31, wid = t >> 5;
    int v = tsum;
    #pragma unroll
    for (int d = 1; d < 32; d <<= 1) {
        int n = __shfl_up_sync(0xffffffffu, v, d);
        if (lane >= d) v += n;
    }
    if (lane == 31) warpSums[wid] = v;
    __syncthreads();
    if (wid == 0 && lane < 8) {
        int wv = warpSums[lane];
        #pragma unroll
        for (int d = 1; d < 8; d <<= 1) {
            int n = __shfl_up_sync(0xffu, wv, d);
            if (lane >= d) wv += n;
        }
        warpSums[lane] = wv;
    }
    __syncthreads();
    if (wid == 0) {
        int T = warpSums[7];
        if (b == 0) {
            if (lane == 0) {
                g_prefv[0] = T;
                __threadfence();
                *(volatile int*)&g_flag[0] = 2;
                sPrefix = 0;
            }
        } else {
            if (lane == 0) {
                g_aggv[b] = T;
                __threadfence();
                *(volatile int*)&g_flag[b] = 1;
            }
            int run = 0;
            int baseJ = b - 1;
            while (true) {
                int j = baseJ - lane;
                int f = (j >= 0) ? *(volatile int*)&g_flag[j] : 3;
                while (__any_sync(0xffffffffu, f == 0)) {
                    if (f == 0) f = *(volatile int*)&g_flag[j];
                }
                __threadfence();
                int val = 0;
                if (j >= 0) val = (f == 2) ? g_prefv[j] : g_aggv[j];
                unsigned m2 = __ballot_sync(0xffffffffu, (j >= 0) && (f == 2));
                int stopLane = m2 ? (__ffs(m2) - 1) : 32;
                int contrib = (lane <= stopLane && j >= 0) ? val : 0;
                #pragma unroll
                for (int o = 16; o > 0; o >>= 1)
                    contrib += __shfl_down_sync(0xffffffffu, contrib, o);
                contrib = __shfl_sync(0xffffffffu, contrib, 0);
                run += contrib;
                if (m2) break;
                baseJ -= 32;
            }
            if (lane == 0) {
                sPrefix = run;
                g_prefv[b] = run + T;
                __threadfence();
                *(volatile int*)&g_flag[b] = 2;
            }
        }
    }
    __syncthreads();
    int exc = v - tsum + (wid > 0 ? warpSums[wid - 1] : 0) + sPrefix;
    int e0 = exc, e1 = exc + c0, e2 = e1 + c1, e3 = e2 + c2;
    if (base + 0 < NN) { g_offs[base + 0] = e0; g_cursor[base + 0] = e0; }
    if (base + 1 < NN) { g_offs[base + 1] = e1; g_cursor[base + 1] = e1; }
    if (base + 2 < NN) { g_offs[base + 2] = e2; g_cursor[base + 2] = e2; }
    if (base + 3 < NN) { g_offs[base + 3] = e3; g_cursor[base + 3] = e3; }
    if (base + 0 == NN - 1) g_offs[NN] = e1;
    if (base + 1 == NN - 1) g_offs[NN] = e2;
    if (base + 2 == NN - 1) g_offs[NN] = e3;
    if (base + 3 == NN - 1) g_offs[NN] = e3 + c3;
}

// sentinels into <=3 padding slots per node; re-zero counts+flags for replay.
// Touches ONLY padding slots -> disjoint from scatter_k's writes.
__global__ void pad_k() {
    int i = blockIdx.x * blockDim.x + threadIdx.x;
    if (i == 0) { g_as1[NN] = -1e38f; g_as2[NN] = -1e38f; }
    if (i < 128) g_flag[i] = 0;
    if (i < NN) {
        int c = g_counts[i];
        int start = g_offs[i] + c;
        int end = g_offs[i + 1];
        for (int k = start; k < end; k++) g_csr[k] = NN;
        g_counts[i] = 0;
    }
}

__global__ void scatter_k(const int4* __restrict__ src4, const int4* __restrict__ dst4) {
    int i = blockIdx.x * blockDim.x + threadIdx.x;
    if (i < EE / 4) {
        int4 s = src4[i];
        int4 d = dst4[i];
        g_csr[atomicAdd(&g_cursor[d.x], 1)] = s.x;
        g_csr[atomicAdd(&g_cursor[d.y], 1)] = s.y;
        g_csr[atomicAdd(&g_cursor[d.z], 1)] = s.z;
        g_csr[atomicAdd(&g_cursor[d.w], 1)] = s.w;
    }
}

// ---------------- dense: H16 = fp16(X@W), a_s, a_d (row range) -------------
// 256 threads, 128 rows x 64 cols per block, 8x4 outputs/thread, fma2.
__global__ void __launch_bounds__(256) gemm_att_k(
    const float* __restrict__ X, const float* __restrict__ W,
    const float* __restrict__ attS, const float* __restrict__ attD,
    __half2* __restrict__ H16, float* __restrict__ AS, float* __restrict__ AD,
    int rowStart, int rowEnd)
{
    __shared__ float sW[64 * 64];        // [k][c]
    __shared__ float sXT[64 * 130];      // [k][r], 128 rows + pad
    __shared__ float sAtt[128];
    int tid = threadIdx.x;
    int rowBase = rowStart + blockIdx.x * 128;

    #pragma unroll
    for (int i = 0; i < 4; i++)
        ((float4*)sW)[tid + 256 * i] = ((const float4*)W)[tid + 256 * i];
    if (tid < 128) sAtt[tid] = (tid < 64) ? attS[tid] : attD[tid - 64];

    {
        int r = tid >> 1;                 // 0..127
        int k0 = (tid & 1) * 32;          // 0 or 32
        int grow = rowBase + r;
        bool rv = grow < rowEnd;
        const float4* xp = (const float4*)(X + (size_t)(rv ? grow : 0) * 64) + (k0 >> 2);
        #pragma unroll
        for (int i = 0; i < 8; i++) {
            float4 v = rv ? xp[i] : make_float4(0.f, 0.f, 0.f, 0.f);
            int kb = k0 + 4 * i;
            sXT[(kb + 0) * 130 + r] = v.x;
            sXT[(kb + 1) * 130 + r] = v.y;
            sXT[(kb + 2) * 130 + r] = v.z;
            sXT[(kb + 3) * 130 + r] = v.w;
        }
    }
    __syncthreads();

    int cg = (tid & 15) * 4;      // 16 col groups x 4 cols
    int rg = (tid >> 4) * 8;      // 16 row groups x 8 rows

    unsigned long long acc[4][4];
    #pragma unroll
    for (int a = 0; a < 4; a++)
        #pragma unroll
        for (int b = 0; b < 4; b++) acc[a][b] = 0ull;

    #pragma unroll 2
    for (int k = 0; k < 64; k++) {
        const float* xb = &sXT[k * 130 + rg];
        unsigned long long x01 = *(const unsigned long long*)(xb);
        unsigned long long x23 = *(const unsigned long long*)(xb + 2);
        unsigned long long x45 = *(const unsigned long long*)(xb + 4);
        unsigned long long x67 = *(const unsigned long long*)(xb + 6);
        float4 wv = *(const float4*)(&sW[(k << 6) + cg]);
        unsigned long long w0 = dup2(wv.x), w1 = dup2(wv.y);
        unsigned long long w2 = dup2(wv.z), w3 = dup2(wv.w);
        acc[0][0] = fma2(x01, w0, acc[0][0]);
        acc[0][1] = fma2(x01, w1, acc[0][1]);
        acc[0][2] = fma2(x01, w2, acc[0][2]);
        acc[0][3] = fma2(x01, w3, acc[0][3]);
        acc[1][0] = fma2(x23, w0, acc[1][0]);
        acc[1][1] = fma2(x23, w1, acc[1][1]);
        acc[1][2] = fma2(x23, w2, acc[1][2]);
        acc[1][3] = fma2(x23, w3, acc[1][3]);
        acc[2][0] = fma2(x45, w0, acc[2][0]);
        acc[2][1] = fma2(x45, w1, acc[2][1]);
        acc[2][2] = fma2(x45, w2, acc[2][2]);
        acc[2][3] = fma2(x45, w3, acc[2][3]);
        acc[3][0] = fma2(x67, w0, acc[3][0]);
        acc[3][1] = fma2(x67, w1, acc[3][1]);
        acc[3][2] = fma2(x67, w2, acc[3][2]);
        acc[3][3] = fma2(x67, w3, acc[3][3]);
    }

    float hv[8][4];
    #pragma unroll
    for (int rp = 0; rp < 4; rp++)
        #pragma unroll
        for (int c = 0; c < 4; c++)
            unpack2(acc[rp][c], hv[2 * rp][c], hv[2 * rp + 1][c]);

    float pas[8], pad_[8];
    #pragma unroll
    for (int r = 0; r < 8; r++) {
        float s = 0.f, d = 0.f;
        #pragma unroll
        for (int c = 0; c < 4; c++) {
            s = fmaf(hv[r][c], sAtt[cg + c], s);
            d = fmaf(hv[r][c], sAtt[64 + cg + c], d);
        }
        pas[r] = s; pad_[r] = d;
    }
    #pragma unroll
    for (int off = 8; off >= 1; off >>= 1) {
        #pragma unroll
        for (int r = 0; r < 8; r++) {
            pas[r]  += __shfl_xor_sync(0xffffffffu, pas[r],  off, 16);
            pad_[r] += __shfl_xor_sync(0xffffffffu, pad_[r], off, 16);
        }
    }
    if ((tid & 15) == 0) {
        #pragma unroll
        for (int r = 0; r < 8; r++) {
            int grow = rowBase + rg + r;
            if (grow < rowEnd) { AS[grow] = pas[r]; AD[grow] = pad_[r]; }
        }
    }
    #pragma unroll
    for (int r = 0; r < 8; r++) {
        int grow = rowBase + rg + r;
        if (grow < rowEnd) {
            union { __half2 h[2]; uint2 u; } cv;
            cv.h[0] = __floats2half2_rn(hv[r][0], hv[r][1]);
            cv.h[1] = __floats2half2_rn(hv[r][2], hv[r][3]);
            *(uint2*)(H16 + (size_t)grow * 32 + (cg >> 1)) = cv.u;
        }
    }
}

// ---------------- sparse aggregate: quarter-warp split per dst (range) -----
__global__ void __launch_bounds__(256) aggregate_k(
    const __half2* __restrict__ H16,
    const float* __restrict__ AS, const float* __restrict__ AD,
    const float* __restrict__ bias,
    float* __restrict__ OUT, int do_relu,
    int dstStart, int dstEnd)
{
    int dst = dstStart + ((blockIdx.x * blockDim.x + threadIdx.x) >> 5);
    int lane = threadIdx.x & 31;
    if (dst >= dstEnd) return;
    int grp = lane >> 3;         // 0..3
    int gl = lane & 7;           // covers cols [8*gl, 8*gl+8)
    int j0 = __ldg(&g_offs[dst]);
    int j1 = __ldg(&g_offs[dst + 1]);
    float ad = __ldg(&AD[dst]);
    float s = 0.f;
    float a0 = 0.f, a1 = 0.f, a2 = 0.f, a3 = 0.f;
    float a4 = 0.f, a5 = 0.f, a6 = 0.f, a7 = 0.f;

    for (int jA = j0; jA < j1; jA += 16) {
        int jSelf = jA + (grp << 2);
        float vm = (jSelf < j1) ? 1.f : 0.f;
        int jc = (jSelf < j1) ? jSelf : j0;
        int4 i4 = *(const int4*)&g_csr[jc];
        float e0 = __ldg(&AS[i4.x]) + ad;
        float e1 = __ldg(&AS[i4.y]) + ad;
        float e2 = __ldg(&AS[i4.z]) + ad;
        float e3 = __ldg(&AS[i4.w]) + ad;
        uint4 v0 = __ldg(&((const uint4*)(H16 + ((size_t)i4.x << 5)))[gl]);
        uint4 v1 = __ldg(&((const uint4*)(H16 + ((size_t)i4.y << 5)))[gl]);
        uint4 v2 = __ldg(&((const uint4*)(H16 + ((size_t)i4.z << 5)))[gl]);
        uint4 v3 = __ldg(&((const uint4*)(H16 + ((size_t)i4.w << 5)))[gl]);
        e0 = e0 > 0.f ? e0 : 0.2f * e0;
        e1 = e1 > 0.f ? e1 : 0.2f * e1;
        e2 = e2 > 0.f ? e2 : 0.2f * e2;
        e3 = e3 > 0.f ? e3 : 0.2f * e3;
        float w0 = __expf(fminf(e0, 70.f)) * vm;     // sentinel/invalid -> 0
        float w1 = __expf(fminf(e1, 70.f)) * vm;
        float w2 = __expf(fminf(e2, 70.f)) * vm;
        float w3 = __expf(fminf(e3, 70.f)) * vm;
        s += (w0 + w1) + (w2 + w3);
        float2 f;
        f = __half22float2(*(__half2*)&v0.x); a0 = fmaf(w0, f.x, a0); a1 = fmaf(w0, f.y, a1);
        f = __half22float2(*(__half2*)&v0.y); a2 = fmaf(w0, f.x, a2); a3 = fmaf(w0, f.y, a3);
        f = __half22float2(*(__half2*)&v0.z); a4 = fmaf(w0, f.x, a4); a5 = fmaf(w0, f.y, a5);
        f = __half22float2(*(__half2*)&v0.w); a6 = fmaf(w0, f.x, a6); a7 = fmaf(w0, f.y, a7);
        f = __half22float2(*(__half2*)&v1.x); a0 = fmaf(w1, f.x, a0); a1 = fmaf(w1, f.y, a1);
        f = __half22float2(*(__half2*)&v1.y); a2 = fmaf(w1, f.x, a2); a3 = fmaf(w1, f.y, a3);
        f = __half22float2(*(__half2*)&v1.z); a4 = fmaf(w1, f.x, a4); a5 = fmaf(w1, f.y, a5);
        f = __half22float2(*(__half2*)&v1.w); a6 = fmaf(w1, f.x, a6); a7 = fmaf(w1, f.y, a7);
        f = __half22float2(*(__half2*)&v2.x); a0 = fmaf(w2, f.x, a0); a1 = fmaf(w2, f.y, a1);
        f = __half22float2(*(__half2*)&v2.y); a2 = fmaf(w2, f.x, a2); a3 = fmaf(w2, f.y, a3);
        f = __half22float2(*(__half2*)&v2.z); a4 = fmaf(w2, f.x, a4); a5 = fmaf(w2, f.y, a5);
        f = __half22float2(*(__half2*)&v2.w); a6 = fmaf(w2, f.x, a6); a7 = fmaf(w2, f.y, a7);
        f = __half22float2(*(__half2*)&v3.x); a0 = fmaf(w3, f.x, a0); a1 = fmaf(w3, f.y, a1);
        f = __half22float2(*(__half2*)&v3.y); a2 = fmaf(w3, f.x, a2); a3 = fmaf(w3, f.y, a3);
        f = __half22float2(*(__half2*)&v3.z); a4 = fmaf(w3, f.x, a4); a5 = fmaf(w3, f.y, a5);
        f = __half22float2(*(__half2*)&v3.w); a6 = fmaf(w3, f.x, a6); a7 = fmaf(w3, f.y, a7);
    }
    #pragma unroll
    for (int off = 8; off <= 16; off <<= 1) {
        s  += __shfl_xor_sync(0xffffffffu, s,  off);
        a0 += __shfl_xor_sync(0xffffffffu, a0, off);
        a1 += __shfl_xor_sync(0xffffffffu, a1, off);
        a2 += __shfl_xor_sync(0xffffffffu, a2, off);
        a3 += __shfl_xor_sync(0xffffffffu, a3, off);
        a4 += __shfl_xor_sync(0xffffffffu, a4, off);
        a5 += __shfl_xor_sync(0xffffffffu, a5, off);
        a6 += __shfl_xor_sync(0xffffffffu, a6, off);
        a7 += __shfl_xor_sync(0xffffffffu, a7, off);
    }
    if (lane < 8) {
        float inv = 1.f / (s + 1e-16f);
        float4 b0 = __ldg(&((const float4*)bias)[2 * gl]);
        float4 b1 = __ldg(&((const float4*)bias)[2 * gl + 1]);
        float4 o0, o1;
        o0.x = fmaf(a0, inv, b0.x);
        o0.y = fmaf(a1, inv, b0.y);
        o0.z = fmaf(a2, inv, b0.z);
        o0.w = fmaf(a3, inv, b0.w);
        o1.x = fmaf(a4, inv, b1.x);
        o1.y = fmaf(a5, inv, b1.y);
        o1.z = fmaf(a6, inv, b1.z);
        o1.w = fmaf(a7, inv, b1.w);
        if (do_relu) {
            o0.x = fmaxf(o0.x, 0.f); o0.y = fmaxf(o0.y, 0.f);
            o0.z = fmaxf(o0.z, 0.f); o0.w = fmaxf(o0.w, 0.f);
            o1.x = fmaxf(o1.x, 0.f); o1.y = fmaxf(o1.y, 0.f);
            o1.z = fmaxf(o1.z, 0.f); o1.w = fmaxf(o1.w, 0.f);
        }
        float4* op = (float4*)(OUT + ((size_t)dst << 6));
        op[2 * gl] = o0;
        op[2 * gl + 1] = o1;
    }
}

// ---------------- launch ---------------------------------------------------
extern "C" void kernel_launch(void* const* d_in, const int* in_sizes, int n_in,
                              void* d_out, int out_size)
{
    const float* x   = (const float*)d_in[0];
    const int*   ei  = (const int*)  d_in[1];
    const float* W1  = (const float*)d_in[2];
    const float* as1 = (const float*)d_in[3];
    const float* ad1 = (const float*)d_in[4];
    const float* b1  = (const float*)d_in[5];
    const float* W2  = (const float*)d_in[6];
    const float* as2 = (const float*)d_in[7];
    const float* ad2 = (const float*)d_in[8];
    const float* b2  = (const float*)d_in[9];
    float* out = (float*)d_out;

    const int* src = ei;
    const int* dst = ei + EE;

    __half2 *pHa, *pHb; float *pZ, *pAS1, *pAD1, *pAS2, *pAD2;
    cudaGetSymbolAddress((void**)&pHa,  g_h16a);
    cudaGetSymbolAddress((void**)&pHb,  g_h16b);
    cudaGetSymbolAddress((void**)&pZ,   g_z);
    cudaGetSymbolAddress((void**)&pAS1, g_as1);
    cudaGetSymbolAddress((void**)&pAD1, g_ad1);
    cudaGetSymbolAddress((void**)&pAS2, g_as2);
    cudaGetSymbolAddress((void**)&pAD2, g_ad2);

    static cudaStream_t s2 = nullptr;
    static cudaEvent_t evFork = nullptr, evJoin = nullptr, evScan = nullptr;
    static cudaEvent_t evA1c0 = nullptr, evG2c0 = nullptr;
    if (s2 == nullptr) {
        cudaStreamCreateWithFlags(&s2, cudaStreamNonBlocking);
        cudaEventCreateWithFlags(&evFork, cudaEventDisableTiming);
        cudaEventCreateWithFlags(&evJoin, cudaEventDisableTiming);
        cudaEventCreateWithFlags(&evScan, cudaEventDisableTiming);
        cudaEventCreateWithFlags(&evA1c0, cudaEventDisableTiming);
        cudaEventCreateWithFlags(&evG2c0, cudaEventDisableTiming);
    }

    // fork: gemm1 on s2 (depends only on x/W1), then pad (after scan)
    cudaEventRecord(evFork, 0);
    cudaStreamWaitEvent(s2, evFork, 0);
    gemm_att_k<<<(NN + 127) / 128, 256, 0, s2>>>(x, W1, as1, ad1, pHa, pAS1, pAD1, 0, NN);

    // CSR build on main stream (counts/flags pre-zeroed: init + pad_k)
    hist_k<<<(EE / 4 + 255) / 256, 256>>>((const int4*)dst);
    scan_k<<<(NN + 1023) / 1024, 256>>>();
    cudaEventRecord(evScan, 0);

    // pad on s2 behind gemm1, concurrent with scatter (disjoint CSR slots)
    cudaStreamWaitEvent(s2, evScan, 0);
    pad_k<<<(NN + 255) / 256, 256, 0, s2>>>();
    cudaEventRecord(evJoin, s2);

    scatter_k<<<(EE / 4 + 255) / 256, 256>>>((const int4*)src, (const int4*)dst);

    // join, then pipelined layer boundary (race-free via double buffers):
    //   agg1[0,C)  -> { gemm2[0,C)->Hb on s2  ||  agg1[C,NN) reads Ha on main }
    //   -> gemm2[C,NN) -> join -> agg2 reads Hb
    cudaStreamWaitEvent(0, evJoin, 0);
    aggregate_k<<<(CHUNK * 32) / 256, 256>>>(pHa, pAS1, pAD1, b1, pZ, 1, 0, CHUNK);
    cudaEventRecord(evA1c0, 0);

    cudaStreamWaitEvent(s2, evA1c0, 0);
    gemm_att_k<<<CHUNK / 128, 256, 0, s2>>>(pZ, W2, as2, ad2, pHb, pAS2, pAD2, 0, CHUNK);
    cudaEventRecord(evG2c0, s2);

    aggregate_k<<<((NN - CHUNK) * 32 + 255) / 256, 256>>>(pHa, pAS1, pAD1, b1, pZ, 1, CHUNK, NN);
    gemm_att_k<<<(NN - CHUNK + 127) / 128, 256>>>(pZ, W2, as2, ad2, pHb, pAS2, pAD2, CHUNK, NN);

    // agg2 needs full Hb from both gemm2 chunks
    cudaStreamWaitEvent(0, evG2c0, 0);
    aggregate_k<<<(NN * 32 + 255) / 256, 256>>>(pHb, pAS2, pAD2, b2, out, 0, 0, NN);
}